// round 11
// baseline (speedup 1.0000x reference)
#include <cuda_runtime.h>

// ---------------- problem constants ----------------
#define NYD 256
#define NXD 256
#define PML 20
#define PADW 22            // PML + FD_PAD
#define NP  300            // padded grid edge
#define NT  250
#define NSHOT 2
#define NSRC 8
#define NREC 64
#define DTC 0.0005f

// strips
#define SSTR 60            // strips per shot
#define RROW 5             // rows per strip
#define NCTA (NSHOT * SSTR)   // 120 CTAs (<=148 SMs -> all resident, spin-sync safe)
#define BX 160             // one thread = one column PAIR (2*tid, 2*tid+1)
#define BY 6               // 5 compute rows + 1 service row
#define NTHR (BX*BY)       // 960 threads, 30 warps
#define NPX (NP + 8)       // 308: 4 guard columns each side, float2-aligned
#define BAR1_CNT (25*32 + 32)   // compute warps + flag warp = 832

// FD coefficients folded with 1/h and 1/h^2 (h = 5)
#define C1A ( 1.0f/60.0f)
#define C1B (-2.0f/15.0f)
#define C1C ( 2.0f/15.0f)
#define C1D (-1.0f/60.0f)
#define C2A (-1.0f/300.0f)
#define C2B ( 4.0f/75.0f)
#define C2C (-0.1f)

// ---------------- persistent device state ----------------
__device__ float g_wf  [2][NSHOT][NP][NP];
__device__ float g_v2dt2[NP][NP];
__device__ float g_a[NP], g_b[NP];
__device__ int   g_sy[NSHOT*NSRC], g_sx[NSHOT*NSRC];
__device__ float g_sscale[NSHOT*NSRC];
__device__ int   g_ry[NSHOT*NREC], g_rx[NSHOT*NREC];
__device__ int   g_flag[NCTA * 32];          // 128B-padded flags

// ---------------- packed f32x2 helpers ----------------
__device__ __forceinline__ float2 ffma2(float2 a, float2 b, float2 c) {
    float2 d;
    asm("{\n\t.reg .b64 A,B,C,D;\n\t"
        "mov.b64 A,{%2,%3};\n\tmov.b64 B,{%4,%5};\n\tmov.b64 C,{%6,%7};\n\t"
        "fma.rn.f32x2 D,A,B,C;\n\t"
        "mov.b64 {%0,%1},D;\n\t}"
        : "=f"(d.x), "=f"(d.y)
        : "f"(a.x), "f"(a.y), "f"(b.x), "f"(b.y), "f"(c.x), "f"(c.y));
    return d;
}
__device__ __forceinline__ float2 fmul2(float2 a, float2 b) {
    float2 d;
    asm("{\n\t.reg .b64 A,B,D;\n\t"
        "mov.b64 A,{%2,%3};\n\tmov.b64 B,{%4,%5};\n\t"
        "mul.rn.f32x2 D,A,B;\n\t"
        "mov.b64 {%0,%1},D;\n\t}"
        : "=f"(d.x), "=f"(d.y)
        : "f"(a.x), "f"(a.y), "f"(b.x), "f"(b.y));
    return d;
}
__device__ __forceinline__ float2 fadd2(float2 a, float2 b) {
    float2 d;
    asm("{\n\t.reg .b64 A,B,D;\n\t"
        "mov.b64 A,{%2,%3};\n\tmov.b64 B,{%4,%5};\n\t"
        "add.rn.f32x2 D,A,B;\n\t"
        "mov.b64 {%0,%1},D;\n\t}"
        : "=f"(d.x), "=f"(d.y)
        : "f"(a.x), "f"(a.y), "f"(b.x), "f"(b.y));
    return d;
}
__device__ __forceinline__ float2 bc(float s) { return make_float2(s, s); }
__device__ __forceinline__ float2 sh(float2 a, float2 b) { return make_float2(a.y, b.x); }
__device__ __forceinline__ float2 ld2s(const float* p) { return *(const float2*)p; }
__device__ __forceinline__ void   st2s(float* p, float2 v) { *(float2*)p = v; }
__device__ __forceinline__ float2 ldg2cg(const float* p) {
    float2 v;
    asm volatile("ld.global.cg.v2.f32 {%0,%1}, [%2];" : "=f"(v.x), "=f"(v.y) : "l"(p));
    return v;
}
__device__ __forceinline__ void stg2cg(float* p, float2 v) {
    asm volatile("st.global.cg.v2.f32 [%0], {%1,%2};" :: "l"(p), "f"(v.x), "f"(v.y) : "memory");
}

// ---------------- scoped sync helpers ----------------
__device__ __forceinline__ int poll_flag(const int* p) {
    int v; asm volatile("ld.acquire.gpu.b32 %0, [%1];" : "=r"(v) : "l"(p)); return v;
}
__device__ __forceinline__ void set_flag(int* p, int v) {
    asm volatile("st.release.gpu.b32 [%0], %1;" :: "l"(p), "r"(v) : "memory");
}
#define BAR_ARRIVE(id, cnt) asm volatile("bar.arrive %0, %1;" :: "r"(id), "r"(cnt) : "memory")
#define BAR_SYNCN(id, cnt)  asm volatile("bar.sync %0, %1;"   :: "r"(id), "r"(cnt) : "memory")

// ---------------- init kernel ----------------
__global__ void init_all(const float* __restrict__ v,
                         const int* __restrict__ sl, const int* __restrict__ rl)
{
    int idx = blockIdx.x * blockDim.x + threadIdx.x;
    int stride = gridDim.x * blockDim.x;

    float* wf = &g_wf[0][0][0][0];
    const int NSTATE = 2 * NSHOT * NP * NP;
    for (int i = idx; i < NSTATE; i += stride) wf[i] = 0.f;

    for (int i = idx; i < NP * NP; i += stride) {
        int y = i / NP, x = i - y * NP;
        int vy = min(max(y - PADW, 0), NYD - 1);
        int vx = min(max(x - PADW, 0), NXD - 1);
        float vv = v[vy * NXD + vx];
        (&g_v2dt2[0][0])[i] = vv * vv * (DTC * DTC);
    }

    for (int i = idx; i < NP; i += stride) {
        double fi = (double)i;
        double frac = fmax(22.0 - fi, fi - 277.0) / (double)PML;
        frac = fmin(fmax(frac, 0.0), 1.0);
        double sm   = 3.0 * 4000.0 * log(1000.0) / (2.0 * PML * 5.0);
        double sig  = sm * frac * frac;
        double alp  = 3.141592653589793 * 25.0 * (1.0 - frac);
        double bb   = exp(-(sig + alp) * (double)DTC);
        double aa   = sig / (sig + alp + 1e-9) * (bb - 1.0);
        g_a[i] = (float)aa;
        g_b[i] = (float)bb;
    }

    for (int i = idx; i < NCTA * 32; i += stride) g_flag[i] = 0;

    if (idx == 0) {
        bool s64 = true;
        for (int k = 1; k < NSHOT * NSRC * 2; k += 2) if (sl[k] != 0) { s64 = false; break; }
        for (int s = 0; s < NSHOT * NSRC; s++) {
            int y = s64 ? sl[4*s]     : sl[2*s];
            int x = s64 ? sl[4*s + 2] : sl[2*s + 1];
            g_sy[s] = y + PADW; g_sx[s] = x + PADW;
            float vv = v[y * NXD + x];
            g_sscale[s] = vv * vv * (DTC * DTC);
        }
        bool r64 = true;
        for (int k = 1; k < NSHOT * NREC * 2; k += 2) if (rl[k] != 0) { r64 = false; break; }
        for (int s = 0; s < NSHOT * NREC; s++) {
            int y = r64 ? rl[4*s]     : rl[2*s];
            int x = r64 ? rl[4*s + 2] : rl[2*s + 1];
            g_ry[s] = y + PADW; g_rx[s] = x + PADW;
        }
    }
}

// ---------------- persistent wave kernel (warp-specialized, acyclic flags) ----------------
// Block (160, 6): ty 0..4 compute; ty 5 = service row.
//   service warp 0  (tid 0..31):  flag warp — bar1-sync with compute, release flag,
//                                 record receivers, prefetch amp.
//   service warps 1-4 (tid 32..159): staging — poll neighbor flag >= t+1, stage halo
//                                 for step t+1 into buffer 1-p (overlaps compute of t).
// Flag t+1 depends ONLY on our compute t -> no circular wait.
__global__ void __launch_bounds__(NTHR, 1)
wave_kernel(const float* __restrict__ amp, float* __restrict__ out)
{
    const int bid   = blockIdx.x;
    const int shot  = bid / SSTR;
    const int strip = bid - shot * SSTR;
    const int y0    = strip * RROW;
    const int tid   = threadIdx.x;
    const int r     = threadIdx.y;          // 0..4 compute row, 5 = service
    const int tidl  = threadIdx.x + BX * threadIdx.y;
    const int c0    = 2 * tid;
    const bool act  = (c0 < NP);
    const bool isService = (r == 5);
    const int cc    = c0 + 4;               // float2-aligned smem column

    __shared__ float s_w[2][13][NPX];       // double-buffered wf rows y0-4 .. y0+8
    __shared__ float s_axp[NPX], s_bxp[NPX];
    __shared__ float s_aA[9], s_bA[9];
    __shared__ float s_amp[2][NSRC];        // double-buffered source amplitudes
    __shared__ int   s_nsrc, s_nrec;
    __shared__ int   s_src_r[NSRC], s_src_c[NSRC], s_src_idx[NSRC];
    __shared__ float s_src_scale[NSRC];
    __shared__ short s_rec_r[NREC], s_rec_c[NREC];
    __shared__ int   s_rec_out[NREC];

    // zero guard columns in BOTH buffers (cols 0..3 and NP+4..NP+7)
    if (tidl < 26) {
        int b = tidl / 13, row = tidl % 13;
        #pragma unroll
        for (int g = 0; g < 4; g++) {
            s_w[b][row][g] = 0.f;
            s_w[b][row][NP + 4 + g] = 0.f;
        }
    }
    for (int i = tidl; i < NPX; i += NTHR) {
        int col = i - 4;
        bool in = (col >= 0 && col < NP);
        s_axp[i] = in ? g_a[col] : 0.f;
        s_bxp[i] = in ? g_b[col] : 0.f;
    }
    if (tidl >= 32 && tidl < 41) {
        int j = tidl - 32;
        int y = y0 - 2 + j;
        bool in = (y >= 0 && y < NP);
        s_aA[j] = in ? g_a[y] : 0.f;
        s_bA[j] = in ? g_b[y] : 0.f;
    }
    if (tidl == 0) {
        int ns = 0;
        for (int i = 0; i < NSRC; i++) {
            int s = shot * NSRC + i;
            int rr = g_sy[s] - y0;
            if (rr >= 0 && rr < RROW) {
                s_src_r[ns] = rr; s_src_c[ns] = g_sx[s];
                s_src_idx[ns] = s; s_src_scale[ns] = g_sscale[s]; ns++;
            }
        }
        s_nsrc = ns;
        int nr = 0;
        for (int i = 0; i < NREC; i++) {
            int s = shot * NREC + i;
            int rr = g_ry[s] - y0;
            if (rr >= 0 && rr < RROW) {
                s_rec_r[nr] = (short)rr; s_rec_c[nr] = (short)g_rx[s];
                s_rec_out[nr] = s * NT; nr++;
            }
        }
        s_nrec = nr;
    }

    // ---- per-thread register state (compute rows only) ----
    float2 wc = {0.f,0.f}, wm = {0.f,0.f};
    float2 zy = {0.f,0.f}, zx = {0.f,0.f};
    float2 pyr[5] = {{0.f,0.f},{0.f,0.f},{0.f,0.f},{0.f,0.f},{0.f,0.f}};
    float2 pxL = {0.f,0.f}, pxM = {0.f,0.f}, pxR = {0.f,0.f};
    float2 v2 = {0.f,0.f}, axM = {0.f,0.f}, bxM = {0.f,0.f};
    if (act && !isService) {
        v2  = ld2s(&g_v2dt2[y0 + r][c0]);
        axM = make_float2(g_a[c0], g_a[c0 + 1]);
        bxM = make_float2(g_b[c0], g_b[c0 + 1]);
    }
    const float2 vC1A = bc(C1A), vC1B = bc(C1B), vC1C = bc(C1C), vC1D = bc(C1D);
    const float2 vC2A = bc(C2A), vC2B = bc(C2B), vC2C = bc(C2C);

    const float* wfb[2] = { &g_wf[0][shot][0][0], &g_wf[1][shot][0][0] };
    __syncthreads();   // tables ready

    // ---- prologue: stage buffer 0 for t=0 (wavefield all zero) ----
    if (act) {
        if (isService) {
            #pragma unroll
            for (int k = 0; k < 4; k++) {
                st2s(&s_w[0][k][cc],     make_float2(0.f, 0.f));
                st2s(&s_w[0][9 + k][cc], make_float2(0.f, 0.f));
            }
        } else {
            st2s(&s_w[0][4 + r][cc], make_float2(0.f, 0.f));
        }
    }
    if (isService && tid < NSRC) {
        s_amp[0][tid] = (tid < s_nsrc) ? amp[s_src_idx[tid] * NT + 0] : 0.f;
    }
    __syncthreads();

    for (int t = 0; t < NT; t++) {
        const int p = t & 1;
        float* __restrict__ wfn = (float*)wfb[1 - p];
        float (* __restrict__ sw)[NPX] = s_w[p];

        if (!isService) {
            // ================= COMPUTE WARPS =================
            if (act) {
                float2 w0 = ld2s(&sw[r + 0][cc]);
                float2 w1 = ld2s(&sw[r + 1][cc]);
                float2 w2 = ld2s(&sw[r + 2][cc]);
                float2 w3 = ld2s(&sw[r + 3][cc]);
                float2 w4 = wc;
                float2 w5 = ld2s(&sw[r + 5][cc]);
                float2 w6 = ld2s(&sw[r + 6][cc]);
                float2 w7 = ld2s(&sw[r + 7][cc]);
                float2 w8 = ld2s(&sw[r + 8][cc]);

                // psi_y recursion at 5 rows
                {
                    float2 d;
                    d = ffma2(vC1A, w0, ffma2(vC1B, w1, ffma2(vC1C, w3, fmul2(vC1D, w4))));
                    pyr[0] = ffma2(bc(s_bA[r + 0]), pyr[0], fmul2(bc(s_aA[r + 0]), d));
                    d = ffma2(vC1A, w1, ffma2(vC1B, w2, ffma2(vC1C, w4, fmul2(vC1D, w5))));
                    pyr[1] = ffma2(bc(s_bA[r + 1]), pyr[1], fmul2(bc(s_aA[r + 1]), d));
                    d = ffma2(vC1A, w2, ffma2(vC1B, w3, ffma2(vC1C, w5, fmul2(vC1D, w6))));
                    pyr[2] = ffma2(bc(s_bA[r + 2]), pyr[2], fmul2(bc(s_aA[r + 2]), d));
                    d = ffma2(vC1A, w3, ffma2(vC1B, w4, ffma2(vC1C, w6, fmul2(vC1D, w7))));
                    pyr[3] = ffma2(bc(s_bA[r + 3]), pyr[3], fmul2(bc(s_aA[r + 3]), d));
                    d = ffma2(vC1A, w4, ffma2(vC1B, w5, ffma2(vC1C, w7, fmul2(vC1D, w8))));
                    pyr[4] = ffma2(bc(s_bA[r + 4]), pyr[4], fmul2(bc(s_aA[r + 4]), d));
                }

                float2 XL2 = ld2s(&sw[r + 4][cc - 4]);
                float2 XL  = ld2s(&sw[r + 4][cc - 2]);
                float2 XM  = w4;
                float2 XR  = ld2s(&sw[r + 4][cc + 2]);
                float2 XR2 = ld2s(&sw[r + 4][cc + 4]);
                float2 s1 = sh(XL2, XL), s2 = sh(XL, XM), s3 = sh(XM, XR), s4 = sh(XR, XR2);

                // psi_x recursion at 3 column pairs
                {
                    float2 axL = ld2s(&s_axp[cc - 2]), bxL = ld2s(&s_bxp[cc - 2]);
                    float2 axR = ld2s(&s_axp[cc + 2]), bxR = ld2s(&s_bxp[cc + 2]);
                    float2 d;
                    d = ffma2(vC1A, XL2, ffma2(vC1B, s1, ffma2(vC1C, s2, fmul2(vC1D, XM))));
                    pxL = ffma2(bxL, pxL, fmul2(axL, d));
                    d = ffma2(vC1A, XL, ffma2(vC1B, s2, ffma2(vC1C, s3, fmul2(vC1D, XR))));
                    pxM = ffma2(bxM, pxM, fmul2(axM, d));
                    d = ffma2(vC1A, XM, ffma2(vC1B, s3, ffma2(vC1C, s4, fmul2(vC1D, XR2))));
                    pxR = ffma2(bxR, pxR, fmul2(axR, d));
                }

                float2 d2y = ffma2(vC2A, w2, ffma2(vC2B, w3, ffma2(vC2C, w4,
                             ffma2(vC2B, w5, fmul2(vC2A, w6)))));
                float2 d2x = ffma2(vC2A, XL, ffma2(vC2B, s2, ffma2(vC2C, XM,
                             ffma2(vC2B, s3, fmul2(vC2A, XR)))));
                float2 dpy = ffma2(vC1A, pyr[0], ffma2(vC1B, pyr[1],
                             ffma2(vC1C, pyr[3], fmul2(vC1D, pyr[4]))));
                float2 dpx = ffma2(vC1A, pxL, ffma2(vC1B, sh(pxL, pxM),
                             ffma2(vC1C, sh(pxM, pxR), fmul2(vC1D, pxR))));

                float2 syv = fadd2(d2y, dpy);
                float2 sxv = fadd2(d2x, dpx);
                float2 nzy = ffma2(bc(s_bA[r + 2]), zy, fmul2(bc(s_aA[r + 2]), syv));
                float2 nzx = ffma2(bxM, zx, fmul2(axM, sxv));
                zy = nzy; zx = nzx;
                float2 lap = fadd2(fadd2(fadd2(syv, sxv), nzy), nzx);
                float2 base = make_float2(2.0f * wc.x - wm.x, 2.0f * wc.y - wm.y);
                float2 wp = ffma2(v2, lap, base);

                const int ns = s_nsrc;
                for (int k = 0; k < ns; k++) {
                    if (s_src_r[k] == r && (s_src_c[k] >> 1) == tid) {
                        float add = s_src_scale[k] * s_amp[p][k];
                        if (s_src_c[k] & 1) wp.y += add; else wp.x += add;
                    }
                }
                stg2cg(&wfn[(y0 + r) * NP + c0], wp);       // for neighbors + recording
                st2s(&s_w[1 - p][4 + r][cc], wp);           // for own CTA next step
                wm = wc; wc = wp;
            }
            BAR_ARRIVE(1, BAR1_CNT);    // signal: step-t writes issued
        } else if (tid < 32) {
            // ================= FLAG WARP =================
            if (t + 1 < NT && tid < NSRC) {     // amp prefetch (independent)
                s_amp[1 - p][tid] = (tid < s_nsrc) ? amp[s_src_idx[tid] * NT + (t + 1)] : 0.f;
            }
            BAR_SYNCN(1, BAR1_CNT);             // wait for compute warps' STGs
            if (tid == 0) set_flag(&g_flag[bid * 32], t + 1);
            if (t > 0) {                         // record receivers of step t-1
                const float* __restrict__ wrec = wfb[p];
                for (int k = tid; k < s_nrec; k += 32)
                    out[s_rec_out[k] + (t - 1)] =
                        __ldcg(&wrec[(y0 + s_rec_r[k]) * NP + s_rec_c[k]]);
            }
        } else {
            // ================= STAGING WARPS (tid 32..159) =================
            // stage halo for step t+1 into buffer 1-p; waits only on NEIGHBOR compute
            if (t + 1 < NT) {
                const float* __restrict__ wfnx = wfb[1 - p];   // wf(t+1) values
                const int sid = tid - 32;                       // 0..127
                if (sid < 64) {
                    if (strip > 0) {
                        const int* fp = &g_flag[(bid - 1) * 32];
                        while (poll_flag(fp) < t + 1) { }
                        #pragma unroll
                        for (int row = 0; row < 4; row++) {
                            int y = y0 - 4 + row;
                            for (int k = sid; k < NP / 2; k += 64)
                                st2s(&s_w[1 - p][row][2 * k + 4],
                                     ldg2cg(&wfnx[y * NP + 2 * k]));
                        }
                    }
                } else {
                    if (strip < SSTR - 1) {
                        const int* fp = &g_flag[(bid + 1) * 32];
                        while (poll_flag(fp) < t + 1) { }
                        const int sid2 = sid - 64;
                        #pragma unroll
                        for (int row = 0; row < 4; row++) {
                            int y = y0 + 5 + row;
                            for (int k = sid2; k < NP / 2; k += 64)
                                st2s(&s_w[1 - p][9 + row][2 * k + 4],
                                     ldg2cg(&wfnx[y * NP + 2 * k]));
                        }
                    }
                }
            }
        }

        __syncthreads();   // bar2: staging + compute STS + flag all done
    }

    // final receiver recording for step NT-1 (written to wfb[NT&1])
    {
        const float* wfl = wfb[NT & 1];
        for (int k = tidl; k < s_nrec; k += NTHR)
            out[s_rec_out[k] + (NT - 1)] =
                __ldcg(&wfl[(y0 + s_rec_r[k]) * NP + s_rec_c[k]]);
    }
}

// ---------------- launch ----------------
extern "C" void kernel_launch(void* const* d_in, const int* in_sizes, int n_in,
                              void* d_out, int out_size)
{
    const float* v   = (const float*)d_in[0];
    const float* amp = (const float*)d_in[1];
    const int*   sl  = (const int*)d_in[2];
    const int*   rl  = (const int*)d_in[3];

    init_all<<<NCTA, 256>>>(v, sl, rl);
    dim3 blk(BX, BY);
    wave_kernel<<<NCTA, blk>>>(amp, (float*)d_out);
}

// round 12
// speedup vs baseline: 1.6624x; 1.6624x over previous
#include <cuda_runtime.h>

// ---------------- problem constants ----------------
#define NYD 256
#define NXD 256
#define PML 20
#define PADW 22            // PML + FD_PAD
#define NP  300            // padded grid edge
#define NT  250
#define NSHOT 2
#define NSRC 8
#define NREC 64
#define DTC 0.0005f

// strips
#define SSTR 60            // strips per shot
#define RROW 5             // rows per strip
#define NCTA (NSHOT * SSTR)   // 120 CTAs (<=148 SMs -> all resident, spin-sync safe)
#define BX 160             // one thread = one column PAIR (2*tid, 2*tid+1)
#define BY 5
#define NTHR (BX*BY)       // 800 threads, 25 warps
#define NPX (NP + 8)       // 308: 4 guard columns each side, float2-aligned

// FD coefficients folded with 1/h and 1/h^2 (h = 5)
#define C1A ( 1.0f/60.0f)
#define C1B (-2.0f/15.0f)
#define C1C ( 2.0f/15.0f)
#define C1D (-1.0f/60.0f)
#define C2A (-1.0f/300.0f)
#define C2B ( 4.0f/75.0f)
#define C2C (-0.1f)

// ---------------- persistent device state ----------------
__device__ float g_wf  [2][NSHOT][NP][NP];
__device__ float g_v2dt2[NP][NP];
__device__ float g_a[NP], g_b[NP];
__device__ int   g_sy[NSHOT*NSRC], g_sx[NSHOT*NSRC];
__device__ float g_sscale[NSHOT*NSRC];
__device__ int   g_ry[NSHOT*NREC], g_rx[NSHOT*NREC];
__device__ int   g_flag[NCTA * 32];          // 128B-padded flags

// ---------------- packed f32x2 helpers ----------------
__device__ __forceinline__ float2 ffma2(float2 a, float2 b, float2 c) {
    float2 d;
    asm("{\n\t.reg .b64 A,B,C,D;\n\t"
        "mov.b64 A,{%2,%3};\n\tmov.b64 B,{%4,%5};\n\tmov.b64 C,{%6,%7};\n\t"
        "fma.rn.f32x2 D,A,B,C;\n\t"
        "mov.b64 {%0,%1},D;\n\t}"
        : "=f"(d.x), "=f"(d.y)
        : "f"(a.x), "f"(a.y), "f"(b.x), "f"(b.y), "f"(c.x), "f"(c.y));
    return d;
}
__device__ __forceinline__ float2 fmul2(float2 a, float2 b) {
    float2 d;
    asm("{\n\t.reg .b64 A,B,D;\n\t"
        "mov.b64 A,{%2,%3};\n\tmov.b64 B,{%4,%5};\n\t"
        "mul.rn.f32x2 D,A,B;\n\t"
        "mov.b64 {%0,%1},D;\n\t}"
        : "=f"(d.x), "=f"(d.y)
        : "f"(a.x), "f"(a.y), "f"(b.x), "f"(b.y));
    return d;
}
__device__ __forceinline__ float2 fadd2(float2 a, float2 b) {
    float2 d;
    asm("{\n\t.reg .b64 A,B,D;\n\t"
        "mov.b64 A,{%2,%3};\n\tmov.b64 B,{%4,%5};\n\t"
        "add.rn.f32x2 D,A,B;\n\t"
        "mov.b64 {%0,%1},D;\n\t}"
        : "=f"(d.x), "=f"(d.y)
        : "f"(a.x), "f"(a.y), "f"(b.x), "f"(b.y));
    return d;
}
__device__ __forceinline__ float2 bc(float s) { return make_float2(s, s); }
__device__ __forceinline__ float2 sh(float2 a, float2 b) { return make_float2(a.y, b.x); }
__device__ __forceinline__ float2 ld2s(const float* p) { return *(const float2*)p; }
__device__ __forceinline__ void   st2s(float* p, float2 v) { *(float2*)p = v; }
__device__ __forceinline__ float2 ldg2cg(const float* p) {
    float2 v;
    asm volatile("ld.global.cg.v2.f32 {%0,%1}, [%2];" : "=f"(v.x), "=f"(v.y) : "l"(p));
    return v;
}
__device__ __forceinline__ void stg2cg(float* p, float2 v) {
    asm volatile("st.global.cg.v2.f32 [%0], {%1,%2};" :: "l"(p), "f"(v.x), "f"(v.y) : "memory");
}

// ---------------- scoped sync helpers ----------------
__device__ __forceinline__ int poll_relaxed(const int* p) {
    int v; asm volatile("ld.relaxed.gpu.b32 %0, [%1];" : "=r"(v) : "l"(p)); return v;
}
__device__ __forceinline__ int poll_acquire(const int* p) {
    int v; asm volatile("ld.acquire.gpu.b32 %0, [%1];" : "=r"(v) : "l"(p)); return v;
}
__device__ __forceinline__ void set_flag(int* p, int v) {
    asm volatile("st.release.gpu.b32 [%0], %1;" :: "l"(p), "r"(v) : "memory");
}
#define BAR_ARRIVE(id, cnt) asm volatile("bar.arrive %0, %1;" :: "r"(id), "r"(cnt) : "memory")
#define BAR_SYNCN(id, cnt)  asm volatile("bar.sync %0, %1;"   :: "r"(id), "r"(cnt) : "memory")

// ---------------- init kernel ----------------
__global__ void init_all(const float* __restrict__ v,
                         const int* __restrict__ sl, const int* __restrict__ rl)
{
    int idx = blockIdx.x * blockDim.x + threadIdx.x;
    int stride = gridDim.x * blockDim.x;

    float* wf = &g_wf[0][0][0][0];
    const int NSTATE = 2 * NSHOT * NP * NP;
    for (int i = idx; i < NSTATE; i += stride) wf[i] = 0.f;

    for (int i = idx; i < NP * NP; i += stride) {
        int y = i / NP, x = i - y * NP;
        int vy = min(max(y - PADW, 0), NYD - 1);
        int vx = min(max(x - PADW, 0), NXD - 1);
        float vv = v[vy * NXD + vx];
        (&g_v2dt2[0][0])[i] = vv * vv * (DTC * DTC);
    }

    for (int i = idx; i < NP; i += stride) {
        double fi = (double)i;
        double frac = fmax(22.0 - fi, fi - 277.0) / (double)PML;
        frac = fmin(fmax(frac, 0.0), 1.0);
        double sm   = 3.0 * 4000.0 * log(1000.0) / (2.0 * PML * 5.0);
        double sig  = sm * frac * frac;
        double alp  = 3.141592653589793 * 25.0 * (1.0 - frac);
        double bb   = exp(-(sig + alp) * (double)DTC);
        double aa   = sig / (sig + alp + 1e-9) * (bb - 1.0);
        g_a[i] = (float)aa;
        g_b[i] = (float)bb;
    }

    for (int i = idx; i < NCTA * 32; i += stride) g_flag[i] = 0;

    if (idx == 0) {
        bool s64 = true;
        for (int k = 1; k < NSHOT * NSRC * 2; k += 2) if (sl[k] != 0) { s64 = false; break; }
        for (int s = 0; s < NSHOT * NSRC; s++) {
            int y = s64 ? sl[4*s]     : sl[2*s];
            int x = s64 ? sl[4*s + 2] : sl[2*s + 1];
            g_sy[s] = y + PADW; g_sx[s] = x + PADW;
            float vv = v[y * NXD + x];
            g_sscale[s] = vv * vv * (DTC * DTC);
        }
        bool r64 = true;
        for (int k = 1; k < NSHOT * NREC * 2; k += 2) if (rl[k] != 0) { r64 = false; break; }
        for (int s = 0; s < NSHOT * NREC; s++) {
            int y = r64 ? rl[4*s]     : rl[2*s];
            int x = r64 ? rl[4*s + 2] : rl[2*s + 1];
            g_ry[s] = y + PADW; g_rx[s] = x + PADW;
        }
    }
}

// ---------------- persistent wave kernel ----------------
// Block (160, 5): thread = (row r = ty, column pair c0=2*tid, c0+1).
// Per step: stage (lane0 polls, warp loads halo) -> syncthreads -> fused compute
// (psi/zeta register recursions) -> STG wfn + smem receiver capture -> split bar
// -> warp0: flag release + receiver STG (off critical path).
__global__ void __launch_bounds__(NTHR, 1)
wave_kernel(const float* __restrict__ amp, float* __restrict__ out)
{
    const int bid   = blockIdx.x;
    const int shot  = bid / SSTR;
    const int strip = bid - shot * SSTR;
    const int y0    = strip * RROW;
    const int tid   = threadIdx.x;
    const int r     = threadIdx.y;
    const int tidl  = threadIdx.x + BX * threadIdx.y;
    const int c0    = 2 * tid;
    const bool act  = (c0 < NP);
    const int cc    = c0 + 4;

    __shared__ float s_w[2][13][NPX];       // double-buffered wf rows y0-4 .. y0+8
    __shared__ float s_axp[NPX], s_bxp[NPX];
    __shared__ float s_aA[9], s_bA[9];
    __shared__ float s_recval[NREC];        // receiver values captured from registers
    __shared__ int   s_nsrc, s_nrec;
    __shared__ int   s_src_r[NSRC], s_src_c[NSRC], s_src_idx[NSRC];
    __shared__ float s_src_scale[NSRC];
    __shared__ short s_rec_r[NREC], s_rec_c[NREC];
    __shared__ int   s_rec_out[NREC];

    // zero guard columns in BOTH buffers (cols 0..3 and NP+4..NP+7)
    if (tidl < 26) {
        int b = tidl / 13, row = tidl % 13;
        #pragma unroll
        for (int g = 0; g < 4; g++) {
            s_w[b][row][g] = 0.f;
            s_w[b][row][NP + 4 + g] = 0.f;
        }
    }
    for (int i = tidl; i < NPX; i += NTHR) {
        int col = i - 4;
        bool in = (col >= 0 && col < NP);
        s_axp[i] = in ? g_a[col] : 0.f;
        s_bxp[i] = in ? g_b[col] : 0.f;
    }
    if (tidl >= 32 && tidl < 41) {
        int j = tidl - 32;
        int y = y0 - 2 + j;
        bool in = (y >= 0 && y < NP);
        s_aA[j] = in ? g_a[y] : 0.f;
        s_bA[j] = in ? g_b[y] : 0.f;
    }
    if (tidl == 0) {
        int ns = 0;
        for (int i = 0; i < NSRC; i++) {
            int s = shot * NSRC + i;
            int rr = g_sy[s] - y0;
            if (rr >= 0 && rr < RROW) {
                s_src_r[ns] = rr; s_src_c[ns] = g_sx[s];
                s_src_idx[ns] = s; s_src_scale[ns] = g_sscale[s]; ns++;
            }
        }
        s_nsrc = ns;
        int nr = 0;
        for (int i = 0; i < NREC; i++) {
            int s = shot * NREC + i;
            int rr = g_ry[s] - y0;
            if (rr >= 0 && rr < RROW) {
                s_rec_r[nr] = (short)rr; s_rec_c[nr] = (short)g_rx[s];
                s_rec_out[nr] = s * NT; nr++;
            }
        }
        s_nrec = nr;
    }

    // ---- per-thread register state ----
    float2 wc = {0.f,0.f}, wm = {0.f,0.f};
    float2 zy = {0.f,0.f}, zx = {0.f,0.f};
    float2 pyr[5] = {{0.f,0.f},{0.f,0.f},{0.f,0.f},{0.f,0.f},{0.f,0.f}};
    float2 pxL = {0.f,0.f}, pxM = {0.f,0.f}, pxR = {0.f,0.f};
    float2 v2 = {0.f,0.f}, axM = {0.f,0.f}, bxM = {0.f,0.f};
    if (act) {
        v2  = ld2s(&g_v2dt2[y0 + r][c0]);
        axM = make_float2(g_a[c0], g_a[c0 + 1]);
        bxM = make_float2(g_b[c0], g_b[c0 + 1]);
    }
    const float2 vC1A = bc(C1A), vC1B = bc(C1B), vC1C = bc(C1C), vC1D = bc(C1D);
    const float2 vC2A = bc(C2A), vC2B = bc(C2B), vC2C = bc(C2C);

    const float* wfb[2] = { &g_wf[0][shot][0][0], &g_wf[1][shot][0][0] };
    __syncthreads();   // tables ready

    // ---- static per-thread source mapping (sources are fixed for all t) ----
    int sk0 = -1, sk1 = -1, sg0 = 0, sg1 = 0, so0 = 0, so1 = 0;
    float ss0 = 0.f, ss1 = 0.f;
    {
        const int ns = s_nsrc;
        for (int i = 0; i < ns; i++) {
            if (s_src_r[i] == r && (s_src_c[i] >> 1) == tid) {
                if (sk0 < 0) { sk0 = i; sg0 = s_src_idx[i]; so0 = s_src_c[i] & 1; ss0 = s_src_scale[i]; }
                else         { sk1 = i; sg1 = s_src_idx[i]; so1 = s_src_c[i] & 1; ss1 = s_src_scale[i]; }
            }
        }
    }

    for (int t = 0; t < NT; t++) {
        const int p = t & 1;
        const float* __restrict__ wfcg = wfb[p];
        float* __restrict__ wfn        = (float*)wfb[1 - p];
        float (* __restrict__ sw)[NPX] = s_w[p];

        // ---- staging: lane0 polls (relaxed + acquire confirm), warp loads halo ----
        if (r <= 1) {
            if (strip > 0) {
                const int* fp = &g_flag[(bid - 1) * 32];
                if ((tid & 31) == 0) {
                    while (poll_relaxed(fp) < t) { }
                    (void)poll_acquire(fp);
                }
                __syncwarp();
            }
            if (act) {
                #pragma unroll
                for (int k = 0; k < 2; k++) {
                    int wrow = r * 2 + k;              // 0..3
                    int y = y0 - 4 + wrow;
                    float2 hv = (y >= 0) ? ldg2cg(&wfcg[y * NP + c0]) : make_float2(0.f, 0.f);
                    st2s(&sw[wrow][cc], hv);
                }
            }
        } else if (r <= 3) {
            if (strip < SSTR - 1) {
                const int* fp = &g_flag[(bid + 1) * 32];
                if ((tid & 31) == 0) {
                    while (poll_relaxed(fp) < t) { }
                    (void)poll_acquire(fp);
                }
                __syncwarp();
            }
            if (act) {
                #pragma unroll
                for (int k = 0; k < 2; k++) {
                    int wrow = 9 + (r - 2) * 2 + k;    // 9..12
                    int y = y0 - 4 + wrow;
                    float2 hv = (y < NP) ? ldg2cg(&wfcg[y * NP + c0]) : make_float2(0.f, 0.f);
                    st2s(&sw[wrow][cc], hv);
                }
            }
        }
        if (act) st2s(&sw[4 + r][cc], wc);             // own row

        // source amp prefetch (latency overlaps staging/barrier)
        float a0 = 0.f, a1 = 0.f;
        if (sk0 >= 0) a0 = __ldcg(&amp[sg0 * NT + t]);
        if (sk1 >= 0) a1 = __ldcg(&amp[sg1 * NT + t]);

        __syncthreads();

        // ---- fused compute: psi/zeta register recursions + wavefield ----
        if (act) {
            float2 w0 = ld2s(&sw[r + 0][cc]);
            float2 w1 = ld2s(&sw[r + 1][cc]);
            float2 w2 = ld2s(&sw[r + 2][cc]);
            float2 w3 = ld2s(&sw[r + 3][cc]);
            float2 w4 = wc;
            float2 w5 = ld2s(&sw[r + 5][cc]);
            float2 w6 = ld2s(&sw[r + 6][cc]);
            float2 w7 = ld2s(&sw[r + 7][cc]);
            float2 w8 = ld2s(&sw[r + 8][cc]);

            // psi_y recursion at 5 rows
            {
                float2 d;
                d = ffma2(vC1A, w0, ffma2(vC1B, w1, ffma2(vC1C, w3, fmul2(vC1D, w4))));
                pyr[0] = ffma2(bc(s_bA[r + 0]), pyr[0], fmul2(bc(s_aA[r + 0]), d));
                d = ffma2(vC1A, w1, ffma2(vC1B, w2, ffma2(vC1C, w4, fmul2(vC1D, w5))));
                pyr[1] = ffma2(bc(s_bA[r + 1]), pyr[1], fmul2(bc(s_aA[r + 1]), d));
                d = ffma2(vC1A, w2, ffma2(vC1B, w3, ffma2(vC1C, w5, fmul2(vC1D, w6))));
                pyr[2] = ffma2(bc(s_bA[r + 2]), pyr[2], fmul2(bc(s_aA[r + 2]), d));
                d = ffma2(vC1A, w3, ffma2(vC1B, w4, ffma2(vC1C, w6, fmul2(vC1D, w7))));
                pyr[3] = ffma2(bc(s_bA[r + 3]), pyr[3], fmul2(bc(s_aA[r + 3]), d));
                d = ffma2(vC1A, w4, ffma2(vC1B, w5, ffma2(vC1C, w7, fmul2(vC1D, w8))));
                pyr[4] = ffma2(bc(s_bA[r + 4]), pyr[4], fmul2(bc(s_aA[r + 4]), d));
            }

            float2 XL2 = ld2s(&sw[r + 4][cc - 4]);
            float2 XL  = ld2s(&sw[r + 4][cc - 2]);
            float2 XM  = w4;
            float2 XR  = ld2s(&sw[r + 4][cc + 2]);
            float2 XR2 = ld2s(&sw[r + 4][cc + 4]);
            float2 s1 = sh(XL2, XL), s2 = sh(XL, XM), s3 = sh(XM, XR), s4 = sh(XR, XR2);

            // psi_x recursion at 3 column pairs
            {
                float2 axL = ld2s(&s_axp[cc - 2]), bxL = ld2s(&s_bxp[cc - 2]);
                float2 axR = ld2s(&s_axp[cc + 2]), bxR = ld2s(&s_bxp[cc + 2]);
                float2 d;
                d = ffma2(vC1A, XL2, ffma2(vC1B, s1, ffma2(vC1C, s2, fmul2(vC1D, XM))));
                pxL = ffma2(bxL, pxL, fmul2(axL, d));
                d = ffma2(vC1A, XL, ffma2(vC1B, s2, ffma2(vC1C, s3, fmul2(vC1D, XR))));
                pxM = ffma2(bxM, pxM, fmul2(axM, d));
                d = ffma2(vC1A, XM, ffma2(vC1B, s3, ffma2(vC1C, s4, fmul2(vC1D, XR2))));
                pxR = ffma2(bxR, pxR, fmul2(axR, d));
            }

            float2 d2y = ffma2(vC2A, w2, ffma2(vC2B, w3, ffma2(vC2C, w4,
                         ffma2(vC2B, w5, fmul2(vC2A, w6)))));
            float2 d2x = ffma2(vC2A, XL, ffma2(vC2B, s2, ffma2(vC2C, XM,
                         ffma2(vC2B, s3, fmul2(vC2A, XR)))));
            float2 dpy = ffma2(vC1A, pyr[0], ffma2(vC1B, pyr[1],
                         ffma2(vC1C, pyr[3], fmul2(vC1D, pyr[4]))));
            float2 dpx = ffma2(vC1A, pxL, ffma2(vC1B, sh(pxL, pxM),
                         ffma2(vC1C, sh(pxM, pxR), fmul2(vC1D, pxR))));

            float2 syv = fadd2(d2y, dpy);
            float2 sxv = fadd2(d2x, dpx);
            float2 nzy = ffma2(bc(s_bA[r + 2]), zy, fmul2(bc(s_aA[r + 2]), syv));
            float2 nzx = ffma2(bxM, zx, fmul2(axM, sxv));
            zy = nzy; zx = nzx;
            float2 lap = fadd2(fadd2(fadd2(syv, sxv), nzy), nzx);
            float2 base = make_float2(2.0f * wc.x - wm.x, 2.0f * wc.y - wm.y);
            float2 wp = ffma2(v2, lap, base);

            if (sk0 >= 0) { float add = ss0 * a0; if (so0) wp.y += add; else wp.x += add; }
            if (sk1 >= 0) { float add = ss1 * a1; if (so1) wp.y += add; else wp.x += add; }

            stg2cg(&wfn[(y0 + r) * NP + c0], wp);

            // receiver capture: register -> smem (no global reads on critical path)
            const int nr = s_nrec;
            for (int k = 0; k < nr; k++)
                if (s_rec_r[k] == r && (s_rec_c[k] >> 1) == tid)
                    s_recval[k] = (s_rec_c[k] & 1) ? wp.y : wp.x;

            wm = wc; wc = wp;
        }

        // ---- split barrier: warps arrive; warp0 syncs, releases flag, writes out ----
        if (tidl < 32) {
            BAR_SYNCN(1, NTHR);
            if (tidl == 0) set_flag(&g_flag[bid * 32], t + 1);
            const int nr = s_nrec;
            for (int k = tidl; k < nr; k += 32)
                out[s_rec_out[k] + t] = s_recval[k];
        } else {
            BAR_ARRIVE(1, NTHR);
        }
    }
}

// ---------------- launch ----------------
extern "C" void kernel_launch(void* const* d_in, const int* in_sizes, int n_in,
                              void* d_out, int out_size)
{
    const float* v   = (const float*)d_in[0];
    const float* amp = (const float*)d_in[1];
    const int*   sl  = (const int*)d_in[2];
    const int*   rl  = (const int*)d_in[3];

    init_all<<<352, 1024>>>(v, sl, rl);
    dim3 blk(BX, BY);
    wave_kernel<<<NCTA, blk>>>(amp, (float*)d_out);
}

// round 13
// speedup vs baseline: 1.8289x; 1.1001x over previous
#include <cuda_runtime.h>

// ---------------- problem constants ----------------
#define NYD 256
#define NXD 256
#define PML 20
#define PADW 22            // PML + FD_PAD
#define NP  300            // padded grid edge
#define NT  250
#define NSHOT 2
#define NSRC 8
#define NREC 64
#define DTC 0.0005f

// strips
#define SSTR 60            // strips per shot
#define RROW 5             // rows per strip
#define NCTA (NSHOT * SSTR)   // 120 CTAs (<=148 SMs -> all resident, spin-sync safe)
#define BX 160             // one thread = one column PAIR (2*tid, 2*tid+1)
#define BY 5
#define NTHR (BX*BY)       // 800 threads, 25 warps
#define NPX (NP + 8)       // 308: 4 guard columns each side, float2-aligned

// FD coefficients folded with 1/h and 1/h^2 (h = 5)
#define C1A ( 1.0f/60.0f)
#define C1B (-2.0f/15.0f)
#define C1C ( 2.0f/15.0f)
#define C1D (-1.0f/60.0f)
#define C2A (-1.0f/300.0f)
#define C2B ( 4.0f/75.0f)
#define C2C (-0.1f)

// ---------------- persistent device state ----------------
__device__ float g_wf  [2][NSHOT][NP][NP];
__device__ float g_v2dt2[NP][NP];
__device__ float g_a[NP], g_b[NP];
__device__ int   g_sy[NSHOT*NSRC], g_sx[NSHOT*NSRC];
__device__ float g_sscale[NSHOT*NSRC];
__device__ int   g_ry[NSHOT*NREC], g_rx[NSHOT*NREC];
__device__ int   g_flag[NCTA * 32];          // 128B-padded flags

// ---------------- packed f32x2 helpers ----------------
__device__ __forceinline__ float2 ffma2(float2 a, float2 b, float2 c) {
    float2 d;
    asm("{\n\t.reg .b64 A,B,C,D;\n\t"
        "mov.b64 A,{%2,%3};\n\tmov.b64 B,{%4,%5};\n\tmov.b64 C,{%6,%7};\n\t"
        "fma.rn.f32x2 D,A,B,C;\n\t"
        "mov.b64 {%0,%1},D;\n\t}"
        : "=f"(d.x), "=f"(d.y)
        : "f"(a.x), "f"(a.y), "f"(b.x), "f"(b.y), "f"(c.x), "f"(c.y));
    return d;
}
__device__ __forceinline__ float2 fmul2(float2 a, float2 b) {
    float2 d;
    asm("{\n\t.reg .b64 A,B,D;\n\t"
        "mov.b64 A,{%2,%3};\n\tmov.b64 B,{%4,%5};\n\t"
        "mul.rn.f32x2 D,A,B;\n\t"
        "mov.b64 {%0,%1},D;\n\t}"
        : "=f"(d.x), "=f"(d.y)
        : "f"(a.x), "f"(a.y), "f"(b.x), "f"(b.y));
    return d;
}
__device__ __forceinline__ float2 fadd2(float2 a, float2 b) {
    float2 d;
    asm("{\n\t.reg .b64 A,B,D;\n\t"
        "mov.b64 A,{%2,%3};\n\tmov.b64 B,{%4,%5};\n\t"
        "add.rn.f32x2 D,A,B;\n\t"
        "mov.b64 {%0,%1},D;\n\t}"
        : "=f"(d.x), "=f"(d.y)
        : "f"(a.x), "f"(a.y), "f"(b.x), "f"(b.y));
    return d;
}
__device__ __forceinline__ float2 bc(float s) { return make_float2(s, s); }
__device__ __forceinline__ float2 sh(float2 a, float2 b) { return make_float2(a.y, b.x); }
__device__ __forceinline__ float2 ld2s(const float* p) { return *(const float2*)p; }
__device__ __forceinline__ void   st2s(float* p, float2 v) { *(float2*)p = v; }
__device__ __forceinline__ float2 ldg2cg(const float* p) {
    float2 v;
    asm volatile("ld.global.cg.v2.f32 {%0,%1}, [%2];" : "=f"(v.x), "=f"(v.y) : "l"(p));
    return v;
}
__device__ __forceinline__ void stg2cg(float* p, float2 v) {
    asm volatile("st.global.cg.v2.f32 [%0], {%1,%2};" :: "l"(p), "f"(v.x), "f"(v.y) : "memory");
}

// ---------------- scoped sync helpers ----------------
__device__ __forceinline__ int poll_flag(const int* p) {
    int v; asm volatile("ld.acquire.gpu.b32 %0, [%1];" : "=r"(v) : "l"(p)); return v;
}
__device__ __forceinline__ void set_flag(int* p, int v) {
    asm volatile("st.release.gpu.b32 [%0], %1;" :: "l"(p), "r"(v) : "memory");
}
#define BAR_ARRIVE(id, cnt) asm volatile("bar.arrive %0, %1;" :: "r"(id), "r"(cnt) : "memory")
#define BAR_SYNCN(id, cnt)  asm volatile("bar.sync %0, %1;"   :: "r"(id), "r"(cnt) : "memory")

// ---------------- init kernel ----------------
__global__ void init_all(const float* __restrict__ v,
                         const int* __restrict__ sl, const int* __restrict__ rl)
{
    int idx = blockIdx.x * blockDim.x + threadIdx.x;
    int stride = gridDim.x * blockDim.x;

    float* wf = &g_wf[0][0][0][0];
    const int NSTATE = 2 * NSHOT * NP * NP;
    for (int i = idx; i < NSTATE; i += stride) wf[i] = 0.f;

    for (int i = idx; i < NP * NP; i += stride) {
        int y = i / NP, x = i - y * NP;
        int vy = min(max(y - PADW, 0), NYD - 1);
        int vx = min(max(x - PADW, 0), NXD - 1);
        float vv = v[vy * NXD + vx];
        (&g_v2dt2[0][0])[i] = vv * vv * (DTC * DTC);
    }

    for (int i = idx; i < NP; i += stride) {
        double fi = (double)i;
        double frac = fmax(22.0 - fi, fi - 277.0) / (double)PML;
        frac = fmin(fmax(frac, 0.0), 1.0);
        double sm   = 3.0 * 4000.0 * log(1000.0) / (2.0 * PML * 5.0);
        double sig  = sm * frac * frac;
        double alp  = 3.141592653589793 * 25.0 * (1.0 - frac);
        double bb   = exp(-(sig + alp) * (double)DTC);
        double aa   = sig / (sig + alp + 1e-9) * (bb - 1.0);
        g_a[i] = (float)aa;
        g_b[i] = (float)bb;
    }

    for (int i = idx; i < NCTA * 32; i += stride) g_flag[i] = 0;

    if (idx == 0) {
        bool s64 = true;
        for (int k = 1; k < NSHOT * NSRC * 2; k += 2) if (sl[k] != 0) { s64 = false; break; }
        for (int s = 0; s < NSHOT * NSRC; s++) {
            int y = s64 ? sl[4*s]     : sl[2*s];
            int x = s64 ? sl[4*s + 2] : sl[2*s + 1];
            g_sy[s] = y + PADW; g_sx[s] = x + PADW;
            float vv = v[y * NXD + x];
            g_sscale[s] = vv * vv * (DTC * DTC);
        }
        bool r64 = true;
        for (int k = 1; k < NSHOT * NREC * 2; k += 2) if (rl[k] != 0) { r64 = false; break; }
        for (int s = 0; s < NSHOT * NREC; s++) {
            int y = r64 ? rl[4*s]     : rl[2*s];
            int x = r64 ? rl[4*s + 2] : rl[2*s + 1];
            g_ry[s] = y + PADW; g_rx[s] = x + PADW;
        }
    }
}

// ---------------- persistent wave kernel (R9 skeleton + off-path receivers/amp) ----------------
// Block (160, 5): thread = (row r = ty, column pair c0=2*tid, c0+1).
// Per step: stage (per-thread acquire polls + halo LDG) -> syncthreads -> fused
// compute (psi/zeta register recursions, receiver capture to smem) -> split bar
// -> warp0: flag release, then receiver write-out (off critical path).
__global__ void __launch_bounds__(NTHR, 1)
wave_kernel(const float* __restrict__ amp, float* __restrict__ out)
{
    const int bid   = blockIdx.x;
    const int shot  = bid / SSTR;
    const int strip = bid - shot * SSTR;
    const int y0    = strip * RROW;
    const int tid   = threadIdx.x;
    const int r     = threadIdx.y;
    const int tidl  = threadIdx.x + BX * threadIdx.y;
    const int c0    = 2 * tid;
    const bool act  = (c0 < NP);
    const int cc    = c0 + 4;

    __shared__ float s_w[2][13][NPX];       // double-buffered wf rows y0-4 .. y0+8
    __shared__ float s_axp[NPX], s_bxp[NPX];
    __shared__ float s_aA[9], s_bA[9];
    __shared__ float s_recval[NREC];
    __shared__ int   s_nsrc, s_nrec;
    __shared__ int   s_src_r[NSRC], s_src_c[NSRC], s_src_idx[NSRC];
    __shared__ float s_src_scale[NSRC];
    __shared__ short s_rec_r[NREC], s_rec_c[NREC];
    __shared__ int   s_rec_out[NREC];

    // zero guard columns in BOTH buffers (cols 0..3 and NP+4..NP+7)
    if (tidl < 26) {
        int b = tidl / 13, row = tidl % 13;
        #pragma unroll
        for (int g = 0; g < 4; g++) {
            s_w[b][row][g] = 0.f;
            s_w[b][row][NP + 4 + g] = 0.f;
        }
    }
    for (int i = tidl; i < NPX; i += NTHR) {
        int col = i - 4;
        bool in = (col >= 0 && col < NP);
        s_axp[i] = in ? g_a[col] : 0.f;
        s_bxp[i] = in ? g_b[col] : 0.f;
    }
    if (tidl >= 32 && tidl < 41) {
        int j = tidl - 32;
        int y = y0 - 2 + j;
        bool in = (y >= 0 && y < NP);
        s_aA[j] = in ? g_a[y] : 0.f;
        s_bA[j] = in ? g_b[y] : 0.f;
    }
    if (tidl == 0) {
        int ns = 0;
        for (int i = 0; i < NSRC; i++) {
            int s = shot * NSRC + i;
            int rr = g_sy[s] - y0;
            if (rr >= 0 && rr < RROW) {
                s_src_r[ns] = rr; s_src_c[ns] = g_sx[s];
                s_src_idx[ns] = s; s_src_scale[ns] = g_sscale[s]; ns++;
            }
        }
        s_nsrc = ns;
        int nr = 0;
        for (int i = 0; i < NREC; i++) {
            int s = shot * NREC + i;
            int rr = g_ry[s] - y0;
            if (rr >= 0 && rr < RROW) {
                s_rec_r[nr] = (short)rr; s_rec_c[nr] = (short)g_rx[s];
                s_rec_out[nr] = s * NT; nr++;
            }
        }
        s_nrec = nr;
    }

    // ---- per-thread register state ----
    float2 wc = {0.f,0.f}, wm = {0.f,0.f};
    float2 zy = {0.f,0.f}, zx = {0.f,0.f};
    float2 pyr[5] = {{0.f,0.f},{0.f,0.f},{0.f,0.f},{0.f,0.f},{0.f,0.f}};
    float2 pxL = {0.f,0.f}, pxM = {0.f,0.f}, pxR = {0.f,0.f};
    float2 v2 = {0.f,0.f}, axM = {0.f,0.f}, bxM = {0.f,0.f};
    if (act) {
        v2  = ld2s(&g_v2dt2[y0 + r][c0]);
        axM = make_float2(g_a[c0], g_a[c0 + 1]);
        bxM = make_float2(g_b[c0], g_b[c0 + 1]);
    }
    const float2 vC1A = bc(C1A), vC1B = bc(C1B), vC1C = bc(C1C), vC1D = bc(C1D);
    const float2 vC2A = bc(C2A), vC2B = bc(C2B), vC2C = bc(C2C);

    const float* wfb[2] = { &g_wf[0][shot][0][0], &g_wf[1][shot][0][0] };
    __syncthreads();   // tables ready

    // ---- static per-thread source mapping (sources fixed for all t) ----
    int sk0 = -1, sk1 = -1, sg0 = 0, sg1 = 0, so0 = 0, so1 = 0;
    float ss0 = 0.f, ss1 = 0.f;
    {
        const int ns = s_nsrc;
        for (int i = 0; i < ns; i++) {
            if (s_src_r[i] == r && (s_src_c[i] >> 1) == tid) {
                if (sk0 < 0) { sk0 = i; sg0 = s_src_idx[i]; so0 = s_src_c[i] & 1; ss0 = s_src_scale[i]; }
                else         { sk1 = i; sg1 = s_src_idx[i]; so1 = s_src_c[i] & 1; ss1 = s_src_scale[i]; }
            }
        }
    }

    for (int t = 0; t < NT; t++) {
        const int p = t & 1;
        const float* __restrict__ wfcg = wfb[p];
        float* __restrict__ wfn        = (float*)wfb[1 - p];
        float (* __restrict__ sw)[NPX] = s_w[p];

        // ---- staging: per-thread acquire polls precede this thread's halo LDGs ----
        if (act) {
            if (r <= 1) {
                if (strip > 0) {
                    const int* fp = &g_flag[(bid - 1) * 32];
                    while (poll_flag(fp) < t) { }
                }
                #pragma unroll
                for (int k = 0; k < 2; k++) {
                    int wrow = r * 2 + k;              // 0..3
                    int y = y0 - 4 + wrow;
                    float2 hv = (y >= 0) ? ldg2cg(&wfcg[y * NP + c0]) : make_float2(0.f, 0.f);
                    st2s(&sw[wrow][cc], hv);
                }
            } else if (r <= 3) {
                if (strip < SSTR - 1) {
                    const int* fp = &g_flag[(bid + 1) * 32];
                    while (poll_flag(fp) < t) { }
                }
                #pragma unroll
                for (int k = 0; k < 2; k++) {
                    int wrow = 9 + (r - 2) * 2 + k;    // 9..12
                    int y = y0 - 4 + wrow;
                    float2 hv = (y < NP) ? ldg2cg(&wfcg[y * NP + c0]) : make_float2(0.f, 0.f);
                    st2s(&sw[wrow][cc], hv);
                }
            }
            st2s(&sw[4 + r][cc], wc);                  // own row
        }

        // source amp prefetch (latency overlaps staging/barrier)
        float a0 = 0.f, a1 = 0.f;
        if (sk0 >= 0) a0 = __ldcg(&amp[sg0 * NT + t]);
        if (sk1 >= 0) a1 = __ldcg(&amp[sg1 * NT + t]);

        __syncthreads();

        // ---- fused compute: psi/zeta register recursions + wavefield ----
        if (act) {
            float2 w0 = ld2s(&sw[r + 0][cc]);
            float2 w1 = ld2s(&sw[r + 1][cc]);
            float2 w2 = ld2s(&sw[r + 2][cc]);
            float2 w3 = ld2s(&sw[r + 3][cc]);
            float2 w4 = wc;
            float2 w5 = ld2s(&sw[r + 5][cc]);
            float2 w6 = ld2s(&sw[r + 6][cc]);
            float2 w7 = ld2s(&sw[r + 7][cc]);
            float2 w8 = ld2s(&sw[r + 8][cc]);

            // psi_y recursion at 5 rows
            {
                float2 d;
                d = ffma2(vC1A, w0, ffma2(vC1B, w1, ffma2(vC1C, w3, fmul2(vC1D, w4))));
                pyr[0] = ffma2(bc(s_bA[r + 0]), pyr[0], fmul2(bc(s_aA[r + 0]), d));
                d = ffma2(vC1A, w1, ffma2(vC1B, w2, ffma2(vC1C, w4, fmul2(vC1D, w5))));
                pyr[1] = ffma2(bc(s_bA[r + 1]), pyr[1], fmul2(bc(s_aA[r + 1]), d));
                d = ffma2(vC1A, w2, ffma2(vC1B, w3, ffma2(vC1C, w5, fmul2(vC1D, w6))));
                pyr[2] = ffma2(bc(s_bA[r + 2]), pyr[2], fmul2(bc(s_aA[r + 2]), d));
                d = ffma2(vC1A, w3, ffma2(vC1B, w4, ffma2(vC1C, w6, fmul2(vC1D, w7))));
                pyr[3] = ffma2(bc(s_bA[r + 3]), pyr[3], fmul2(bc(s_aA[r + 3]), d));
                d = ffma2(vC1A, w4, ffma2(vC1B, w5, ffma2(vC1C, w7, fmul2(vC1D, w8))));
                pyr[4] = ffma2(bc(s_bA[r + 4]), pyr[4], fmul2(bc(s_aA[r + 4]), d));
            }

            float2 XL2 = ld2s(&sw[r + 4][cc - 4]);
            float2 XL  = ld2s(&sw[r + 4][cc - 2]);
            float2 XM  = w4;
            float2 XR  = ld2s(&sw[r + 4][cc + 2]);
            float2 XR2 = ld2s(&sw[r + 4][cc + 4]);
            float2 s1 = sh(XL2, XL), s2 = sh(XL, XM), s3 = sh(XM, XR), s4 = sh(XR, XR2);

            // psi_x recursion at 3 column pairs
            {
                float2 axL = ld2s(&s_axp[cc - 2]), bxL = ld2s(&s_bxp[cc - 2]);
                float2 axR = ld2s(&s_axp[cc + 2]), bxR = ld2s(&s_bxp[cc + 2]);
                float2 d;
                d = ffma2(vC1A, XL2, ffma2(vC1B, s1, ffma2(vC1C, s2, fmul2(vC1D, XM))));
                pxL = ffma2(bxL, pxL, fmul2(axL, d));
                d = ffma2(vC1A, XL, ffma2(vC1B, s2, ffma2(vC1C, s3, fmul2(vC1D, XR))));
                pxM = ffma2(bxM, pxM, fmul2(axM, d));
                d = ffma2(vC1A, XM, ffma2(vC1B, s3, ffma2(vC1C, s4, fmul2(vC1D, XR2))));
                pxR = ffma2(bxR, pxR, fmul2(axR, d));
            }

            float2 d2y = ffma2(vC2A, w2, ffma2(vC2B, w3, ffma2(vC2C, w4,
                         ffma2(vC2B, w5, fmul2(vC2A, w6)))));
            float2 d2x = ffma2(vC2A, XL, ffma2(vC2B, s2, ffma2(vC2C, XM,
                         ffma2(vC2B, s3, fmul2(vC2A, XR)))));
            float2 dpy = ffma2(vC1A, pyr[0], ffma2(vC1B, pyr[1],
                         ffma2(vC1C, pyr[3], fmul2(vC1D, pyr[4]))));
            float2 dpx = ffma2(vC1A, pxL, ffma2(vC1B, sh(pxL, pxM),
                         ffma2(vC1C, sh(pxM, pxR), fmul2(vC1D, pxR))));

            float2 syv = fadd2(d2y, dpy);
            float2 sxv = fadd2(d2x, dpx);
            float2 nzy = ffma2(bc(s_bA[r + 2]), zy, fmul2(bc(s_aA[r + 2]), syv));
            float2 nzx = ffma2(bxM, zx, fmul2(axM, sxv));
            zy = nzy; zx = nzx;
            float2 lap = fadd2(fadd2(fadd2(syv, sxv), nzy), nzx);
            float2 base = make_float2(2.0f * wc.x - wm.x, 2.0f * wc.y - wm.y);
            float2 wp = ffma2(v2, lap, base);

            if (sk0 >= 0) { float add = ss0 * a0; if (so0) wp.y += add; else wp.x += add; }
            if (sk1 >= 0) { float add = ss1 * a1; if (so1) wp.y += add; else wp.x += add; }

            stg2cg(&wfn[(y0 + r) * NP + c0], wp);       // for neighbors
            st2s(&s_w[1 - p][4 + r][cc], wp);           // for own CTA next step

            // receiver capture: register -> smem (no global reads on critical path)
            const int nr = s_nrec;
            for (int k = 0; k < nr; k++)
                if (s_rec_r[k] == r && (s_rec_c[k] >> 1) == tid)
                    s_recval[k] = (s_rec_c[k] & 1) ? wp.y : wp.x;

            wm = wc; wc = wp;
        }

        // ---- split barrier: warps arrive; warp0 syncs, releases flag, writes out ----
        if (tidl < 32) {
            BAR_SYNCN(1, NTHR);
            if (tidl == 0) set_flag(&g_flag[bid * 32], t + 1);
            const int nr = s_nrec;
            for (int k = tidl; k < nr; k += 32)
                out[s_rec_out[k] + t] = s_recval[k];
        } else {
            BAR_ARRIVE(1, NTHR);
        }
    }
}

// ---------------- launch ----------------
extern "C" void kernel_launch(void* const* d_in, const int* in_sizes, int n_in,
                              void* d_out, int out_size)
{
    const float* v   = (const float*)d_in[0];
    const float* amp = (const float*)d_in[1];
    const int*   sl  = (const int*)d_in[2];
    const int*   rl  = (const int*)d_in[3];

    init_all<<<NCTA, 256>>>(v, sl, rl);
    dim3 blk(BX, BY);
    wave_kernel<<<NCTA, blk>>>(amp, (float*)d_out);
}

// round 14
// speedup vs baseline: 1.9012x; 1.0395x over previous
#include <cuda_runtime.h>

// ---------------- problem constants ----------------
#define NYD 256
#define NXD 256
#define PML 20
#define PADW 22            // PML + FD_PAD
#define NP  300            // padded grid edge
#define NT  250
#define NSHOT 2
#define NSRC 8
#define NREC 64
#define DTC 0.0005f

// strips
#define SSTR 60            // strips per shot
#define RROW 5             // rows per strip
#define NCTA (NSHOT * SSTR)   // 120 CTAs (<=148 SMs -> all resident, spin-sync safe)
#define BX 160             // one thread = one column PAIR (2*tid, 2*tid+1)
#define BY 5
#define NTHR (BX*BY)       // 800 threads, 25 warps
#define NWARP 25
#define NPX (NP + 8)       // 308: 4 guard columns each side, float2-aligned

// FD coefficients folded with 1/h and 1/h^2 (h = 5)
#define C1A ( 1.0f/60.0f)
#define C1B (-2.0f/15.0f)
#define C1C ( 2.0f/15.0f)
#define C1D (-1.0f/60.0f)
#define C2A (-1.0f/300.0f)
#define C2B ( 4.0f/75.0f)
#define C2C (-0.1f)

// ---------------- persistent device state ----------------
__device__ float g_wf  [2][NSHOT][NP][NP];
__device__ float g_v2dt2[NP][NP];
__device__ float g_a[NP], g_b[NP];
__device__ int   g_sy[NSHOT*NSRC], g_sx[NSHOT*NSRC];
__device__ float g_sscale[NSHOT*NSRC];
__device__ int   g_ry[NSHOT*NREC], g_rx[NSHOT*NREC];
__device__ int   g_flag[NCTA * 32];          // per-CTA progress counters (25/step), 128B-padded

// ---------------- packed f32x2 helpers ----------------
__device__ __forceinline__ float2 ffma2(float2 a, float2 b, float2 c) {
    float2 d;
    asm("{\n\t.reg .b64 A,B,C,D;\n\t"
        "mov.b64 A,{%2,%3};\n\tmov.b64 B,{%4,%5};\n\tmov.b64 C,{%6,%7};\n\t"
        "fma.rn.f32x2 D,A,B,C;\n\t"
        "mov.b64 {%0,%1},D;\n\t}"
        : "=f"(d.x), "=f"(d.y)
        : "f"(a.x), "f"(a.y), "f"(b.x), "f"(b.y), "f"(c.x), "f"(c.y));
    return d;
}
__device__ __forceinline__ float2 fmul2(float2 a, float2 b) {
    float2 d;
    asm("{\n\t.reg .b64 A,B,D;\n\t"
        "mov.b64 A,{%2,%3};\n\tmov.b64 B,{%4,%5};\n\t"
        "mul.rn.f32x2 D,A,B;\n\t"
        "mov.b64 {%0,%1},D;\n\t}"
        : "=f"(d.x), "=f"(d.y)
        : "f"(a.x), "f"(a.y), "f"(b.x), "f"(b.y));
    return d;
}
__device__ __forceinline__ float2 fadd2(float2 a, float2 b) {
    float2 d;
    asm("{\n\t.reg .b64 A,B,D;\n\t"
        "mov.b64 A,{%2,%3};\n\tmov.b64 B,{%4,%5};\n\t"
        "add.rn.f32x2 D,A,B;\n\t"
        "mov.b64 {%0,%1},D;\n\t}"
        : "=f"(d.x), "=f"(d.y)
        : "f"(a.x), "f"(a.y), "f"(b.x), "f"(b.y));
    return d;
}
__device__ __forceinline__ float2 bc(float s) { return make_float2(s, s); }
__device__ __forceinline__ float2 sh(float2 a, float2 b) { return make_float2(a.y, b.x); }
__device__ __forceinline__ float2 ld2s(const float* p) { return *(const float2*)p; }
__device__ __forceinline__ void   st2s(float* p, float2 v) { *(float2*)p = v; }
__device__ __forceinline__ float2 ldg2cg(const float* p) {
    float2 v;
    asm volatile("ld.global.cg.v2.f32 {%0,%1}, [%2];" : "=f"(v.x), "=f"(v.y) : "l"(p));
    return v;
}
__device__ __forceinline__ void stg2cg(float* p, float2 v) {
    asm volatile("st.global.cg.v2.f32 [%0], {%1,%2};" :: "l"(p), "f"(v.x), "f"(v.y) : "memory");
}

// ---------------- scoped sync helpers ----------------
__device__ __forceinline__ int poll_flag(const int* p) {
    int v; asm volatile("ld.acquire.gpu.b32 %0, [%1];" : "=r"(v) : "l"(p)); return v;
}
__device__ __forceinline__ void red_release_add(int* p, int v) {
    asm volatile("red.release.gpu.global.add.u32 [%0], %1;" :: "l"(p), "r"(v) : "memory");
}

// ---------------- init kernel ----------------
__global__ void init_all(const float* __restrict__ v,
                         const int* __restrict__ sl, const int* __restrict__ rl)
{
    int idx = blockIdx.x * blockDim.x + threadIdx.x;
    int stride = gridDim.x * blockDim.x;

    float* wf = &g_wf[0][0][0][0];
    const int NSTATE = 2 * NSHOT * NP * NP;
    for (int i = idx; i < NSTATE; i += stride) wf[i] = 0.f;

    for (int i = idx; i < NP * NP; i += stride) {
        int y = i / NP, x = i - y * NP;
        int vy = min(max(y - PADW, 0), NYD - 1);
        int vx = min(max(x - PADW, 0), NXD - 1);
        float vv = v[vy * NXD + vx];
        (&g_v2dt2[0][0])[i] = vv * vv * (DTC * DTC);
    }

    for (int i = idx; i < NP; i += stride) {
        double fi = (double)i;
        double frac = fmax(22.0 - fi, fi - 277.0) / (double)PML;
        frac = fmin(fmax(frac, 0.0), 1.0);
        double sm   = 3.0 * 4000.0 * log(1000.0) / (2.0 * PML * 5.0);
        double sig  = sm * frac * frac;
        double alp  = 3.141592653589793 * 25.0 * (1.0 - frac);
        double bb   = exp(-(sig + alp) * (double)DTC);
        double aa   = sig / (sig + alp + 1e-9) * (bb - 1.0);
        g_a[i] = (float)aa;
        g_b[i] = (float)bb;
    }

    for (int i = idx; i < NCTA * 32; i += stride) g_flag[i] = 0;

    if (idx == 0) {
        bool s64 = true;
        for (int k = 1; k < NSHOT * NSRC * 2; k += 2) if (sl[k] != 0) { s64 = false; break; }
        for (int s = 0; s < NSHOT * NSRC; s++) {
            int y = s64 ? sl[4*s]     : sl[2*s];
            int x = s64 ? sl[4*s + 2] : sl[2*s + 1];
            g_sy[s] = y + PADW; g_sx[s] = x + PADW;
            float vv = v[y * NXD + x];
            g_sscale[s] = vv * vv * (DTC * DTC);
        }
        bool r64 = true;
        for (int k = 1; k < NSHOT * NREC * 2; k += 2) if (rl[k] != 0) { r64 = false; break; }
        for (int s = 0; s < NSHOT * NREC; s++) {
            int y = r64 ? rl[4*s]     : rl[2*s];
            int x = r64 ? rl[4*s + 2] : rl[2*s + 1];
            g_ry[s] = y + PADW; g_rx[s] = x + PADW;
        }
    }
}

// ---------------- persistent wave kernel (1 barrier/step, per-warp release) ----------------
// Block (160, 5): thread = (row r = ty, column pair c0=2*tid, c0+1).
// Per step: stage (poll counter >= 25*t, halo LDG) -> __syncthreads -> fused compute
// -> STG + STS(next buf) -> __syncwarp -> lane0 red.release +1 -> receiver writes.
__global__ void __launch_bounds__(NTHR, 1)
wave_kernel(const float* __restrict__ amp, float* __restrict__ out)
{
    const int bid   = blockIdx.x;
    const int shot  = bid / SSTR;
    const int strip = bid - shot * SSTR;
    const int y0    = strip * RROW;
    const int tid   = threadIdx.x;
    const int r     = threadIdx.y;
    const int tidl  = threadIdx.x + BX * threadIdx.y;
    const int c0    = 2 * tid;
    const bool act  = (c0 < NP);
    const int cc    = c0 + 4;

    __shared__ float s_w[2][13][NPX];       // double-buffered wf rows y0-4 .. y0+8
    __shared__ float s_axp[NPX], s_bxp[NPX];
    __shared__ float s_aA[9], s_bA[9];
    __shared__ int   s_nsrc, s_nrec;
    __shared__ int   s_src_r[NSRC], s_src_c[NSRC], s_src_idx[NSRC];
    __shared__ float s_src_scale[NSRC];
    __shared__ short s_rec_r[NREC], s_rec_c[NREC];
    __shared__ int   s_rec_out[NREC];

    // zero guard columns in BOTH buffers (cols 0..3 and NP+4..NP+7)
    if (tidl < 26) {
        int b = tidl / 13, row = tidl % 13;
        #pragma unroll
        for (int g = 0; g < 4; g++) {
            s_w[b][row][g] = 0.f;
            s_w[b][row][NP + 4 + g] = 0.f;
        }
    }
    for (int i = tidl; i < NPX; i += NTHR) {
        int col = i - 4;
        bool in = (col >= 0 && col < NP);
        s_axp[i] = in ? g_a[col] : 0.f;
        s_bxp[i] = in ? g_b[col] : 0.f;
    }
    if (tidl >= 32 && tidl < 41) {
        int j = tidl - 32;
        int y = y0 - 2 + j;
        bool in = (y >= 0 && y < NP);
        s_aA[j] = in ? g_a[y] : 0.f;
        s_bA[j] = in ? g_b[y] : 0.f;
    }
    if (tidl == 0) {
        int ns = 0;
        for (int i = 0; i < NSRC; i++) {
            int s = shot * NSRC + i;
            int rr = g_sy[s] - y0;
            if (rr >= 0 && rr < RROW) {
                s_src_r[ns] = rr; s_src_c[ns] = g_sx[s];
                s_src_idx[ns] = s; s_src_scale[ns] = g_sscale[s]; ns++;
            }
        }
        s_nsrc = ns;
        int nr = 0;
        for (int i = 0; i < NREC; i++) {
            int s = shot * NREC + i;
            int rr = g_ry[s] - y0;
            if (rr >= 0 && rr < RROW) {
                s_rec_r[nr] = (short)rr; s_rec_c[nr] = (short)g_rx[s];
                s_rec_out[nr] = s * NT; nr++;
            }
        }
        s_nrec = nr;
    }

    // prologue: own rows of buffer 0 start at zero (staging no longer stores them)
    if (act) st2s(&s_w[0][4 + r][cc], make_float2(0.f, 0.f));

    // ---- per-thread register state ----
    float2 wc = {0.f,0.f}, wm = {0.f,0.f};
    float2 zy = {0.f,0.f}, zx = {0.f,0.f};
    float2 pyr[5] = {{0.f,0.f},{0.f,0.f},{0.f,0.f},{0.f,0.f},{0.f,0.f}};
    float2 pxL = {0.f,0.f}, pxM = {0.f,0.f}, pxR = {0.f,0.f};
    float2 v2 = {0.f,0.f}, axM = {0.f,0.f}, bxM = {0.f,0.f};
    if (act) {
        v2  = ld2s(&g_v2dt2[y0 + r][c0]);
        axM = make_float2(g_a[c0], g_a[c0 + 1]);
        bxM = make_float2(g_b[c0], g_b[c0 + 1]);
    }
    const float2 vC1A = bc(C1A), vC1B = bc(C1B), vC1C = bc(C1C), vC1D = bc(C1D);
    const float2 vC2A = bc(C2A), vC2B = bc(C2B), vC2C = bc(C2C);

    const float* wfb[2] = { &g_wf[0][shot][0][0], &g_wf[1][shot][0][0] };
    __syncthreads();   // tables + prologue ready

    // hoisted x-profile neighbor pairs (constant over time)
    float2 axL = {0.f,0.f}, bxL = {0.f,0.f}, axR = {0.f,0.f}, bxR = {0.f,0.f};
    if (act) {
        axL = ld2s(&s_axp[cc - 2]); bxL = ld2s(&s_bxp[cc - 2]);
        axR = ld2s(&s_axp[cc + 2]); bxR = ld2s(&s_bxp[cc + 2]);
    }

    // ---- static per-thread source mapping ----
    int sk0 = -1, sk1 = -1, sg0 = 0, sg1 = 0, so0 = 0, so1 = 0;
    float ss0 = 0.f, ss1 = 0.f;
    {
        const int ns = s_nsrc;
        for (int i = 0; i < ns; i++) {
            if (s_src_r[i] == r && (s_src_c[i] >> 1) == tid) {
                if (sk0 < 0) { sk0 = i; sg0 = s_src_idx[i]; so0 = s_src_c[i] & 1; ss0 = s_src_scale[i]; }
                else         { sk1 = i; sg1 = s_src_idx[i]; so1 = s_src_c[i] & 1; ss1 = s_src_scale[i]; }
            }
        }
    }
    // ---- static per-thread receiver mapping ----
    int rq0 = -1, rq1 = -1, rb0 = 0, rb1 = 0, ro0 = 0, ro1 = 0;
    {
        const int nr = s_nrec;
        for (int i = 0; i < nr; i++) {
            if (s_rec_r[i] == r && (s_rec_c[i] >> 1) == tid) {
                if (rq0 < 0) { rq0 = i; rb0 = s_rec_out[i]; ro0 = s_rec_c[i] & 1; }
                else         { rq1 = i; rb1 = s_rec_out[i]; ro1 = s_rec_c[i] & 1; }
            }
        }
    }

    int* const myflag = &g_flag[bid * 32];
    const int* upflag = (strip > 0)        ? &g_flag[(bid - 1) * 32] : nullptr;
    const int* dnflag = (strip < SSTR - 1) ? &g_flag[(bid + 1) * 32] : nullptr;
    int thr = 0;   // poll threshold = NWARP * t

    for (int t = 0; t < NT; t++) {
        const int p = t & 1;
        const float* __restrict__ wfcg = wfb[p];
        float* __restrict__ wfn        = (float*)wfb[1 - p];
        float (* __restrict__ sw)[NPX] = s_w[p];

        // ---- staging: per-thread acquire polls precede this thread's halo LDGs ----
        if (act) {
            if (r <= 1) {
                if (upflag) { while (poll_flag(upflag) < thr) { } }
                #pragma unroll
                for (int k = 0; k < 2; k++) {
                    int wrow = r * 2 + k;              // 0..3
                    int y = y0 - 4 + wrow;
                    float2 hv = (y >= 0) ? ldg2cg(&wfcg[y * NP + c0]) : make_float2(0.f, 0.f);
                    st2s(&sw[wrow][cc], hv);
                }
            } else if (r <= 3) {
                if (dnflag) { while (poll_flag(dnflag) < thr) { } }
                #pragma unroll
                for (int k = 0; k < 2; k++) {
                    int wrow = 9 + (r - 2) * 2 + k;    // 9..12
                    int y = y0 - 4 + wrow;
                    float2 hv = (y < NP) ? ldg2cg(&wfcg[y * NP + c0]) : make_float2(0.f, 0.f);
                    st2s(&sw[wrow][cc], hv);
                }
            }
        }

        // source amp prefetch (latency overlaps staging/barrier)
        float a0 = 0.f, a1 = 0.f;
        if (sk0 >= 0) a0 = __ldcg(&amp[sg0 * NT + t]);
        if (sk1 >= 0) a1 = __ldcg(&amp[sg1 * NT + t]);

        __syncthreads();

        // ---- fused compute: psi/zeta register recursions + wavefield ----
        if (act) {
            float2 w0 = ld2s(&sw[r + 0][cc]);
            float2 w1 = ld2s(&sw[r + 1][cc]);
            float2 w2 = ld2s(&sw[r + 2][cc]);
            float2 w3 = ld2s(&sw[r + 3][cc]);
            float2 w4 = wc;
            float2 w5 = ld2s(&sw[r + 5][cc]);
            float2 w6 = ld2s(&sw[r + 6][cc]);
            float2 w7 = ld2s(&sw[r + 7][cc]);
            float2 w8 = ld2s(&sw[r + 8][cc]);

            // psi_y recursion at 5 rows
            {
                float2 d;
                d = ffma2(vC1A, w0, ffma2(vC1B, w1, ffma2(vC1C, w3, fmul2(vC1D, w4))));
                pyr[0] = ffma2(bc(s_bA[r + 0]), pyr[0], fmul2(bc(s_aA[r + 0]), d));
                d = ffma2(vC1A, w1, ffma2(vC1B, w2, ffma2(vC1C, w4, fmul2(vC1D, w5))));
                pyr[1] = ffma2(bc(s_bA[r + 1]), pyr[1], fmul2(bc(s_aA[r + 1]), d));
                d = ffma2(vC1A, w2, ffma2(vC1B, w3, ffma2(vC1C, w5, fmul2(vC1D, w6))));
                pyr[2] = ffma2(bc(s_bA[r + 2]), pyr[2], fmul2(bc(s_aA[r + 2]), d));
                d = ffma2(vC1A, w3, ffma2(vC1B, w4, ffma2(vC1C, w6, fmul2(vC1D, w7))));
                pyr[3] = ffma2(bc(s_bA[r + 3]), pyr[3], fmul2(bc(s_aA[r + 3]), d));
                d = ffma2(vC1A, w4, ffma2(vC1B, w5, ffma2(vC1C, w7, fmul2(vC1D, w8))));
                pyr[4] = ffma2(bc(s_bA[r + 4]), pyr[4], fmul2(bc(s_aA[r + 4]), d));
            }

            float2 XL2 = ld2s(&sw[r + 4][cc - 4]);
            float2 XL  = ld2s(&sw[r + 4][cc - 2]);
            float2 XM  = w4;
            float2 XR  = ld2s(&sw[r + 4][cc + 2]);
            float2 XR2 = ld2s(&sw[r + 4][cc + 4]);
            float2 s1 = sh(XL2, XL), s2 = sh(XL, XM), s3 = sh(XM, XR), s4 = sh(XR, XR2);

            // psi_x recursion at 3 column pairs (profiles hoisted in registers)
            {
                float2 d;
                d = ffma2(vC1A, XL2, ffma2(vC1B, s1, ffma2(vC1C, s2, fmul2(vC1D, XM))));
                pxL = ffma2(bxL, pxL, fmul2(axL, d));
                d = ffma2(vC1A, XL, ffma2(vC1B, s2, ffma2(vC1C, s3, fmul2(vC1D, XR))));
                pxM = ffma2(bxM, pxM, fmul2(axM, d));
                d = ffma2(vC1A, XM, ffma2(vC1B, s3, ffma2(vC1C, s4, fmul2(vC1D, XR2))));
                pxR = ffma2(bxR, pxR, fmul2(axR, d));
            }

            float2 d2y = ffma2(vC2A, w2, ffma2(vC2B, w3, ffma2(vC2C, w4,
                         ffma2(vC2B, w5, fmul2(vC2A, w6)))));
            float2 d2x = ffma2(vC2A, XL, ffma2(vC2B, s2, ffma2(vC2C, XM,
                         ffma2(vC2B, s3, fmul2(vC2A, XR)))));
            float2 dpy = ffma2(vC1A, pyr[0], ffma2(vC1B, pyr[1],
                         ffma2(vC1C, pyr[3], fmul2(vC1D, pyr[4]))));
            float2 dpx = ffma2(vC1A, pxL, ffma2(vC1B, sh(pxL, pxM),
                         ffma2(vC1C, sh(pxM, pxR), fmul2(vC1D, pxR))));

            float2 syv = fadd2(d2y, dpy);
            float2 sxv = fadd2(d2x, dpx);
            float2 nzy = ffma2(bc(s_bA[r + 2]), zy, fmul2(bc(s_aA[r + 2]), syv));
            float2 nzx = ffma2(bxM, zx, fmul2(axM, sxv));
            zy = nzy; zx = nzx;
            float2 lap = fadd2(fadd2(fadd2(syv, sxv), nzy), nzx);
            float2 base = make_float2(2.0f * wc.x - wm.x, 2.0f * wc.y - wm.y);
            float2 wp = ffma2(v2, lap, base);

            if (sk0 >= 0) { float add = ss0 * a0; if (so0) wp.y += add; else wp.x += add; }
            if (sk1 >= 0) { float add = ss1 * a1; if (so1) wp.y += add; else wp.x += add; }

            stg2cg(&wfn[(y0 + r) * NP + c0], wp);       // for neighbors
            st2s(&s_w[1 - p][4 + r][cc], wp);           // for own CTA next step
            wm = wc; wc = wp;
        }

        // ---- per-warp release: this warp's STGs are done -> count it ----
        __syncwarp();
        if ((tidl & 31) == 0) red_release_add(myflag, 1);

        // receiver write-out (off critical path, after release)
        if (rq0 >= 0) out[rb0 + t] = ro0 ? wc.y : wc.x;
        if (rq1 >= 0) out[rb1 + t] = ro1 ? wc.y : wc.x;

        thr += NWARP;
    }
}

// ---------------- launch ----------------
extern "C" void kernel_launch(void* const* d_in, const int* in_sizes, int n_in,
                              void* d_out, int out_size)
{
    const float* v   = (const float*)d_in[0];
    const float* amp = (const float*)d_in[1];
    const int*   sl  = (const int*)d_in[2];
    const int*   rl  = (const int*)d_in[3];

    init_all<<<NCTA, 256>>>(v, sl, rl);
    dim3 blk(BX, BY);
    wave_kernel<<<NCTA, blk>>>(amp, (float*)d_out);
}

// round 15
// speedup vs baseline: 1.9093x; 1.0043x over previous
#include <cuda_runtime.h>

// ---------------- problem constants ----------------
#define NYD 256
#define NXD 256
#define PML 20
#define PADW 22            // PML + FD_PAD
#define NP  300            // padded grid edge
#define NT  250
#define NSHOT 2
#define NSRC 8
#define NREC 64
#define DTC 0.0005f

// strips
#define SSTR 60            // strips per shot
#define RROW 5             // rows per strip
#define NCTA (NSHOT * SSTR)   // 120 CTAs (<=148 SMs -> all resident, spin-sync safe)
#define BX 160             // one thread = one column PAIR (2*tid, 2*tid+1)
#define BY 5
#define NTHR (BX*BY)       // 800 threads, 25 warps
#define NWARP 25
#define NPX (NP + 8)       // 308: 4 guard columns each side, float2-aligned

// FD coefficients folded with 1/h and 1/h^2 (h = 5)
#define C1A ( 1.0f/60.0f)
#define C1B (-2.0f/15.0f)
#define C1C ( 2.0f/15.0f)
#define C1D (-1.0f/60.0f)
#define C2A (-1.0f/300.0f)
#define C2B ( 4.0f/75.0f)
#define C2C (-0.1f)

// ---------------- persistent device state ----------------
__device__ float g_wf  [2][NSHOT][NP][NP];
__device__ float g_v2dt2[NP][NP];
__device__ float g_a[NP], g_b[NP];
__device__ int   g_sy[NSHOT*NSRC], g_sx[NSHOT*NSRC];
__device__ float g_sscale[NSHOT*NSRC];
__device__ int   g_ry[NSHOT*NREC], g_rx[NSHOT*NREC];
__device__ int   g_flag[NCTA * 32];          // per-CTA progress counters (25/step), 128B-padded

// ---------------- packed f32x2 helpers ----------------
__device__ __forceinline__ float2 ffma2(float2 a, float2 b, float2 c) {
    float2 d;
    asm("{\n\t.reg .b64 A,B,C,D;\n\t"
        "mov.b64 A,{%2,%3};\n\tmov.b64 B,{%4,%5};\n\tmov.b64 C,{%6,%7};\n\t"
        "fma.rn.f32x2 D,A,B,C;\n\t"
        "mov.b64 {%0,%1},D;\n\t}"
        : "=f"(d.x), "=f"(d.y)
        : "f"(a.x), "f"(a.y), "f"(b.x), "f"(b.y), "f"(c.x), "f"(c.y));
    return d;
}
__device__ __forceinline__ float2 fmul2(float2 a, float2 b) {
    float2 d;
    asm("{\n\t.reg .b64 A,B,D;\n\t"
        "mov.b64 A,{%2,%3};\n\tmov.b64 B,{%4,%5};\n\t"
        "mul.rn.f32x2 D,A,B;\n\t"
        "mov.b64 {%0,%1},D;\n\t}"
        : "=f"(d.x), "=f"(d.y)
        : "f"(a.x), "f"(a.y), "f"(b.x), "f"(b.y));
    return d;
}
__device__ __forceinline__ float2 fadd2(float2 a, float2 b) {
    float2 d;
    asm("{\n\t.reg .b64 A,B,D;\n\t"
        "mov.b64 A,{%2,%3};\n\tmov.b64 B,{%4,%5};\n\t"
        "add.rn.f32x2 D,A,B;\n\t"
        "mov.b64 {%0,%1},D;\n\t}"
        : "=f"(d.x), "=f"(d.y)
        : "f"(a.x), "f"(a.y), "f"(b.x), "f"(b.y));
    return d;
}
__device__ __forceinline__ float2 bc(float s) { return make_float2(s, s); }
__device__ __forceinline__ float2 sh(float2 a, float2 b) { return make_float2(a.y, b.x); }
__device__ __forceinline__ float2 ld2s(const float* p) { return *(const float2*)p; }
__device__ __forceinline__ void   st2s(float* p, float2 v) { *(float2*)p = v; }
__device__ __forceinline__ float2 ldg2cg(const float* p) {
    float2 v;
    asm volatile("ld.global.cg.v2.f32 {%0,%1}, [%2];" : "=f"(v.x), "=f"(v.y) : "l"(p));
    return v;
}
__device__ __forceinline__ void stg2cg(float* p, float2 v) {
    asm volatile("st.global.cg.v2.f32 [%0], {%1,%2};" :: "l"(p), "f"(v.x), "f"(v.y) : "memory");
}

// ---------------- scoped sync helpers ----------------
__device__ __forceinline__ int poll_flag(const int* p) {
    int v; asm volatile("ld.acquire.gpu.b32 %0, [%1];" : "=r"(v) : "l"(p)); return v;
}
__device__ __forceinline__ void red_release_add(int* p, int v) {
    asm volatile("red.release.gpu.global.add.u32 [%0], %1;" :: "l"(p), "r"(v) : "memory");
}

// ---------------- init kernel ----------------
__global__ void init_all(const float* __restrict__ v,
                         const int* __restrict__ sl, const int* __restrict__ rl)
{
    int idx = blockIdx.x * blockDim.x + threadIdx.x;
    int stride = gridDim.x * blockDim.x;

    float* wf = &g_wf[0][0][0][0];
    const int NSTATE = 2 * NSHOT * NP * NP;
    for (int i = idx; i < NSTATE; i += stride) wf[i] = 0.f;

    for (int i = idx; i < NP * NP; i += stride) {
        int y = i / NP, x = i - y * NP;
        int vy = min(max(y - PADW, 0), NYD - 1);
        int vx = min(max(x - PADW, 0), NXD - 1);
        float vv = v[vy * NXD + vx];
        (&g_v2dt2[0][0])[i] = vv * vv * (DTC * DTC);
    }

    for (int i = idx; i < NP; i += stride) {
        double fi = (double)i;
        double frac = fmax(22.0 - fi, fi - 277.0) / (double)PML;
        frac = fmin(fmax(frac, 0.0), 1.0);
        double sm   = 3.0 * 4000.0 * log(1000.0) / (2.0 * PML * 5.0);
        double sig  = sm * frac * frac;
        double alp  = 3.141592653589793 * 25.0 * (1.0 - frac);
        double bb   = exp(-(sig + alp) * (double)DTC);
        double aa   = sig / (sig + alp + 1e-9) * (bb - 1.0);
        g_a[i] = (float)aa;
        g_b[i] = (float)bb;
    }

    for (int i = idx; i < NCTA * 32; i += stride) g_flag[i] = 0;

    if (idx == 0) {
        bool s64 = true;
        for (int k = 1; k < NSHOT * NSRC * 2; k += 2) if (sl[k] != 0) { s64 = false; break; }
        for (int s = 0; s < NSHOT * NSRC; s++) {
            int y = s64 ? sl[4*s]     : sl[2*s];
            int x = s64 ? sl[4*s + 2] : sl[2*s + 1];
            g_sy[s] = y + PADW; g_sx[s] = x + PADW;
            float vv = v[y * NXD + x];
            g_sscale[s] = vv * vv * (DTC * DTC);
        }
        bool r64 = true;
        for (int k = 1; k < NSHOT * NREC * 2; k += 2) if (rl[k] != 0) { r64 = false; break; }
        for (int s = 0; s < NSHOT * NREC; s++) {
            int y = r64 ? rl[4*s]     : rl[2*s];
            int x = r64 ? rl[4*s + 2] : rl[2*s + 1];
            g_ry[s] = y + PADW; g_rx[s] = x + PADW;
        }
    }
}

// ---------------- persistent wave kernel (1 barrier/step, per-warp release) ----------------
// Block (160, 5): thread = (row r = ty, column pair c0=2*tid, c0+1).
// Per step: stage (poll counter >= 25*t, halo LDG) -> __syncthreads -> fused compute
// -> STG + STS(next buf) -> __syncwarp -> lane0 red.release +1 -> receiver writes.
__global__ void __launch_bounds__(NTHR, 1)
wave_kernel(const float* __restrict__ amp, float* __restrict__ out)
{
    const int bid   = blockIdx.x;
    const int shot  = bid / SSTR;
    const int strip = bid - shot * SSTR;
    const int y0    = strip * RROW;
    const int tid   = threadIdx.x;
    const int r     = threadIdx.y;
    const int tidl  = threadIdx.x + BX * threadIdx.y;
    const int c0    = 2 * tid;
    const bool act  = (c0 < NP);
    const int cc    = c0 + 4;

    __shared__ float s_w[2][13][NPX];       // double-buffered wf rows y0-4 .. y0+8
    __shared__ float s_axp[NPX], s_bxp[NPX];
    __shared__ float s_aA[9], s_bA[9];
    __shared__ int   s_nsrc, s_nrec;
    __shared__ int   s_src_r[NSRC], s_src_c[NSRC], s_src_idx[NSRC];
    __shared__ float s_src_scale[NSRC];
    __shared__ short s_rec_r[NREC], s_rec_c[NREC];
    __shared__ int   s_rec_out[NREC];

    // zero guard columns in BOTH buffers (cols 0..3 and NP+4..NP+7)
    if (tidl < 26) {
        int b = tidl / 13, row = tidl % 13;
        #pragma unroll
        for (int g = 0; g < 4; g++) {
            s_w[b][row][g] = 0.f;
            s_w[b][row][NP + 4 + g] = 0.f;
        }
    }
    for (int i = tidl; i < NPX; i += NTHR) {
        int col = i - 4;
        bool in = (col >= 0 && col < NP);
        s_axp[i] = in ? g_a[col] : 0.f;
        s_bxp[i] = in ? g_b[col] : 0.f;
    }
    if (tidl >= 32 && tidl < 41) {
        int j = tidl - 32;
        int y = y0 - 2 + j;
        bool in = (y >= 0 && y < NP);
        s_aA[j] = in ? g_a[y] : 0.f;
        s_bA[j] = in ? g_b[y] : 0.f;
    }
    if (tidl == 0) {
        int ns = 0;
        for (int i = 0; i < NSRC; i++) {
            int s = shot * NSRC + i;
            int rr = g_sy[s] - y0;
            if (rr >= 0 && rr < RROW) {
                s_src_r[ns] = rr; s_src_c[ns] = g_sx[s];
                s_src_idx[ns] = s; s_src_scale[ns] = g_sscale[s]; ns++;
            }
        }
        s_nsrc = ns;
        int nr = 0;
        for (int i = 0; i < NREC; i++) {
            int s = shot * NREC + i;
            int rr = g_ry[s] - y0;
            if (rr >= 0 && rr < RROW) {
                s_rec_r[nr] = (short)rr; s_rec_c[nr] = (short)g_rx[s];
                s_rec_out[nr] = s * NT; nr++;
            }
        }
        s_nrec = nr;
    }

    // prologue: own rows of buffer 0 start at zero (staging no longer stores them)
    if (act) st2s(&s_w[0][4 + r][cc], make_float2(0.f, 0.f));

    // ---- per-thread register state ----
    float2 wc = {0.f,0.f}, wm = {0.f,0.f};
    float2 zy = {0.f,0.f}, zx = {0.f,0.f};
    float2 pyr[5] = {{0.f,0.f},{0.f,0.f},{0.f,0.f},{0.f,0.f},{0.f,0.f}};
    float2 pxL = {0.f,0.f}, pxM = {0.f,0.f}, pxR = {0.f,0.f};
    float2 v2 = {0.f,0.f}, axM = {0.f,0.f}, bxM = {0.f,0.f};
    if (act) {
        v2  = ld2s(&g_v2dt2[y0 + r][c0]);
        axM = make_float2(g_a[c0], g_a[c0 + 1]);
        bxM = make_float2(g_b[c0], g_b[c0 + 1]);
    }
    const float2 vC1A = bc(C1A), vC1B = bc(C1B), vC1C = bc(C1C), vC1D = bc(C1D);
    const float2 vC2A = bc(C2A), vC2B = bc(C2B), vC2C = bc(C2C);

    const float* wfb[2] = { &g_wf[0][shot][0][0], &g_wf[1][shot][0][0] };
    __syncthreads();   // tables + prologue ready

    // hoisted x-profile neighbor pairs (constant over time)
    float2 axL = {0.f,0.f}, bxL = {0.f,0.f}, axR = {0.f,0.f}, bxR = {0.f,0.f};
    if (act) {
        axL = ld2s(&s_axp[cc - 2]); bxL = ld2s(&s_bxp[cc - 2]);
        axR = ld2s(&s_axp[cc + 2]); bxR = ld2s(&s_bxp[cc + 2]);
    }

    // ---- static per-thread source mapping ----
    int sk0 = -1, sk1 = -1, sg0 = 0, sg1 = 0, so0 = 0, so1 = 0;
    float ss0 = 0.f, ss1 = 0.f;
    {
        const int ns = s_nsrc;
        for (int i = 0; i < ns; i++) {
            if (s_src_r[i] == r && (s_src_c[i] >> 1) == tid) {
                if (sk0 < 0) { sk0 = i; sg0 = s_src_idx[i]; so0 = s_src_c[i] & 1; ss0 = s_src_scale[i]; }
                else         { sk1 = i; sg1 = s_src_idx[i]; so1 = s_src_c[i] & 1; ss1 = s_src_scale[i]; }
            }
        }
    }
    // ---- static per-thread receiver mapping ----
    int rq0 = -1, rq1 = -1, rb0 = 0, rb1 = 0, ro0 = 0, ro1 = 0;
    {
        const int nr = s_nrec;
        for (int i = 0; i < nr; i++) {
            if (s_rec_r[i] == r && (s_rec_c[i] >> 1) == tid) {
                if (rq0 < 0) { rq0 = i; rb0 = s_rec_out[i]; ro0 = s_rec_c[i] & 1; }
                else         { rq1 = i; rb1 = s_rec_out[i]; ro1 = s_rec_c[i] & 1; }
            }
        }
    }

    int* const myflag = &g_flag[bid * 32];
    const int* upflag = (strip > 0)        ? &g_flag[(bid - 1) * 32] : nullptr;
    const int* dnflag = (strip < SSTR - 1) ? &g_flag[(bid + 1) * 32] : nullptr;
    int thr = 0;   // poll threshold = NWARP * t

    for (int t = 0; t < NT; t++) {
        const int p = t & 1;
        const float* __restrict__ wfcg = wfb[p];
        float* __restrict__ wfn        = (float*)wfb[1 - p];
        float (* __restrict__ sw)[NPX] = s_w[p];

        // ---- staging: per-thread acquire polls precede this thread's halo LDGs ----
        if (act) {
            if (r <= 1) {
                if (upflag) { while (poll_flag(upflag) < thr) { } }
                #pragma unroll
                for (int k = 0; k < 2; k++) {
                    int wrow = r * 2 + k;              // 0..3
                    int y = y0 - 4 + wrow;
                    float2 hv = (y >= 0) ? ldg2cg(&wfcg[y * NP + c0]) : make_float2(0.f, 0.f);
                    st2s(&sw[wrow][cc], hv);
                }
            } else if (r <= 3) {
                if (dnflag) { while (poll_flag(dnflag) < thr) { } }
                #pragma unroll
                for (int k = 0; k < 2; k++) {
                    int wrow = 9 + (r - 2) * 2 + k;    // 9..12
                    int y = y0 - 4 + wrow;
                    float2 hv = (y < NP) ? ldg2cg(&wfcg[y * NP + c0]) : make_float2(0.f, 0.f);
                    st2s(&sw[wrow][cc], hv);
                }
            }
        }

        // source amp prefetch (latency overlaps staging/barrier)
        float a0 = 0.f, a1 = 0.f;
        if (sk0 >= 0) a0 = __ldcg(&amp[sg0 * NT + t]);
        if (sk1 >= 0) a1 = __ldcg(&amp[sg1 * NT + t]);

        __syncthreads();

        // ---- fused compute: psi/zeta register recursions + wavefield ----
        if (act) {
            float2 w0 = ld2s(&sw[r + 0][cc]);
            float2 w1 = ld2s(&sw[r + 1][cc]);
            float2 w2 = ld2s(&sw[r + 2][cc]);
            float2 w3 = ld2s(&sw[r + 3][cc]);
            float2 w4 = wc;
            float2 w5 = ld2s(&sw[r + 5][cc]);
            float2 w6 = ld2s(&sw[r + 6][cc]);
            float2 w7 = ld2s(&sw[r + 7][cc]);
            float2 w8 = ld2s(&sw[r + 8][cc]);

            // psi_y recursion at 5 rows
            {
                float2 d;
                d = ffma2(vC1A, w0, ffma2(vC1B, w1, ffma2(vC1C, w3, fmul2(vC1D, w4))));
                pyr[0] = ffma2(bc(s_bA[r + 0]), pyr[0], fmul2(bc(s_aA[r + 0]), d));
                d = ffma2(vC1A, w1, ffma2(vC1B, w2, ffma2(vC1C, w4, fmul2(vC1D, w5))));
                pyr[1] = ffma2(bc(s_bA[r + 1]), pyr[1], fmul2(bc(s_aA[r + 1]), d));
                d = ffma2(vC1A, w2, ffma2(vC1B, w3, ffma2(vC1C, w5, fmul2(vC1D, w6))));
                pyr[2] = ffma2(bc(s_bA[r + 2]), pyr[2], fmul2(bc(s_aA[r + 2]), d));
                d = ffma2(vC1A, w3, ffma2(vC1B, w4, ffma2(vC1C, w6, fmul2(vC1D, w7))));
                pyr[3] = ffma2(bc(s_bA[r + 3]), pyr[3], fmul2(bc(s_aA[r + 3]), d));
                d = ffma2(vC1A, w4, ffma2(vC1B, w5, ffma2(vC1C, w7, fmul2(vC1D, w8))));
                pyr[4] = ffma2(bc(s_bA[r + 4]), pyr[4], fmul2(bc(s_aA[r + 4]), d));
            }

            float2 XL2 = ld2s(&sw[r + 4][cc - 4]);
            float2 XL  = ld2s(&sw[r + 4][cc - 2]);
            float2 XM  = w4;
            float2 XR  = ld2s(&sw[r + 4][cc + 2]);
            float2 XR2 = ld2s(&sw[r + 4][cc + 4]);
            float2 s1 = sh(XL2, XL), s2 = sh(XL, XM), s3 = sh(XM, XR), s4 = sh(XR, XR2);

            // psi_x recursion at 3 column pairs (profiles hoisted in registers)
            {
                float2 d;
                d = ffma2(vC1A, XL2, ffma2(vC1B, s1, ffma2(vC1C, s2, fmul2(vC1D, XM))));
                pxL = ffma2(bxL, pxL, fmul2(axL, d));
                d = ffma2(vC1A, XL, ffma2(vC1B, s2, ffma2(vC1C, s3, fmul2(vC1D, XR))));
                pxM = ffma2(bxM, pxM, fmul2(axM, d));
                d = ffma2(vC1A, XM, ffma2(vC1B, s3, ffma2(vC1C, s4, fmul2(vC1D, XR2))));
                pxR = ffma2(bxR, pxR, fmul2(axR, d));
            }

            float2 d2y = ffma2(vC2A, w2, ffma2(vC2B, w3, ffma2(vC2C, w4,
                         ffma2(vC2B, w5, fmul2(vC2A, w6)))));
            float2 d2x = ffma2(vC2A, XL, ffma2(vC2B, s2, ffma2(vC2C, XM,
                         ffma2(vC2B, s3, fmul2(vC2A, XR)))));
            float2 dpy = ffma2(vC1A, pyr[0], ffma2(vC1B, pyr[1],
                         ffma2(vC1C, pyr[3], fmul2(vC1D, pyr[4]))));
            float2 dpx = ffma2(vC1A, pxL, ffma2(vC1B, sh(pxL, pxM),
                         ffma2(vC1C, sh(pxM, pxR), fmul2(vC1D, pxR))));

            float2 syv = fadd2(d2y, dpy);
            float2 sxv = fadd2(d2x, dpx);
            float2 nzy = ffma2(bc(s_bA[r + 2]), zy, fmul2(bc(s_aA[r + 2]), syv));
            float2 nzx = ffma2(bxM, zx, fmul2(axM, sxv));
            zy = nzy; zx = nzx;
            float2 lap = fadd2(fadd2(fadd2(syv, sxv), nzy), nzx);
            float2 base = make_float2(2.0f * wc.x - wm.x, 2.0f * wc.y - wm.y);
            float2 wp = ffma2(v2, lap, base);

            if (sk0 >= 0) { float add = ss0 * a0; if (so0) wp.y += add; else wp.x += add; }
            if (sk1 >= 0) { float add = ss1 * a1; if (so1) wp.y += add; else wp.x += add; }

            stg2cg(&wfn[(y0 + r) * NP + c0], wp);       // for neighbors
            st2s(&s_w[1 - p][4 + r][cc], wp);           // for own CTA next step
            wm = wc; wc = wp;
        }

        // ---- per-warp release: this warp's STGs are done -> count it ----
        __syncwarp();
        if ((tidl & 31) == 0) red_release_add(myflag, 1);

        // receiver write-out (off critical path, after release)
        if (rq0 >= 0) out[rb0 + t] = ro0 ? wc.y : wc.x;
        if (rq1 >= 0) out[rb1 + t] = ro1 ? wc.y : wc.x;

        thr += NWARP;
    }
}

// ---------------- launch ----------------
extern "C" void kernel_launch(void* const* d_in, const int* in_sizes, int n_in,
                              void* d_out, int out_size)
{
    const float* v   = (const float*)d_in[0];
    const float* amp = (const float*)d_in[1];
    const int*   sl  = (const int*)d_in[2];
    const int*   rl  = (const int*)d_in[3];

    init_all<<<NCTA, 256>>>(v, sl, rl);
    dim3 blk(BX, BY);
    wave_kernel<<<NCTA, blk>>>(amp, (float*)d_out);
}